// round 9
// baseline (speedup 1.0000x reference)
#include <cuda_runtime.h>

#define T_LEN 2048
#define BATCH 64
#define XDIM  64
#define HID   256
#define KH    256            // recurrent K (x part precomputed)
#define KQ    64             // K per quarter-warp

#define NCTA  128            // 2 batch-halves x 64 column-slices
#define NTHR  512            // 16 warps: (warp&3)=column, (warp>>2)=K-quarter

// Static device scratch (no cudaMalloc anywhere)
__device__ float4 g_xz[(size_t)T_LEN * HID * BATCH];   // [t][col][b] pre-activations
__device__ __align__(16) float2 g_h2[2][KH][BATCH];    // tagged h: {h, tag}
__device__ unsigned g_epoch;                           // replay epoch counter

// ---------------- packed f32x2 helpers ----------------
__device__ __forceinline__ unsigned long long fma2_(unsigned long long a,
                                                    unsigned long long b,
                                                    unsigned long long c) {
    unsigned long long d;
    asm("fma.rn.f32x2 %0, %1, %2, %3;" : "=l"(d) : "l"(a), "l"(b), "l"(c));
    return d;
}
__device__ __forceinline__ unsigned long long add2_(unsigned long long a,
                                                    unsigned long long b) {
    unsigned long long d;
    asm("add.rn.f32x2 %0, %1, %2;" : "=l"(d) : "l"(a), "l"(b));
    return d;
}
__device__ __forceinline__ unsigned long long dup2_(float x) {
    unsigned long long d;
    asm("mov.b64 %0, {%1, %1};" : "=l"(d) : "r"(__float_as_uint(x)));
    return d;
}
__device__ __forceinline__ unsigned long long pack2_(float lo, float hi) {
    unsigned long long d;
    asm("mov.b64 %0, {%1, %2};" : "=l"(d) : "r"(__float_as_uint(lo)), "r"(__float_as_uint(hi)));
    return d;
}
__device__ __forceinline__ void unpack2_(unsigned long long v, float& lo, float& hi) {
    unsigned a, b;
    asm("mov.b64 {%0, %1}, %2;" : "=r"(a), "=r"(b) : "l"(v));
    lo = __uint_as_float(a); hi = __uint_as_float(b);
}
__device__ __forceinline__ float sigmoidf_(float x) {
    return 1.0f / (1.0f + __expf(-x));
}
__device__ __forceinline__ float tanh_fast_(float x) {   // 2*sigmoid(2x)-1
    return __fmaf_rn(2.0f, 1.0f / (1.0f + __expf(-2.0f * x)), -1.0f);
}

// Volatile tagged 8B load/store (single transaction -> no tearing)
__device__ __forceinline__ float2 vld2_(const float2* p) {
    float2 v;
    asm volatile("ld.volatile.global.v2.f32 {%0,%1}, [%2];"
                 : "=f"(v.x), "=f"(v.y) : "l"(p));
    return v;
}
__device__ __forceinline__ void vst2_(float2* p, float h, unsigned tag) {
    asm volatile("st.volatile.global.v2.f32 [%0], {%1,%2};"
                 :: "l"(p), "f"(h), "f"(__uint_as_float(tag)) : "memory");
}

// ---------------------------------------------------------------------------
// Pre-kernel: g_xz[t][col][b] = bias + x[b,t,:] . w_ih[4 gate rows of col, :]
// ---------------------------------------------------------------------------
#define PG_COLS 32
__global__ void __launch_bounds__(256) xz_gemm_kernel(
    const float* __restrict__ x, const float* __restrict__ w_ih,
    const float* __restrict__ bias)
{
    extern __shared__ float ps[];
    float (*xs)[65] = (float(*)[65])ps;          // [b][k], padded
    float* ws = ps + 64 * 65;                    // [c][k][q]

    const int t       = blockIdx.y;
    const int colbase = blockIdx.x * PG_COLS;
    const int tid     = threadIdx.x;

    for (int i = tid; i < 64 * 16; i += 256) {
        int b = i >> 4, k4 = i & 15;
        float4 v = *(const float4*)(x + (size_t)b * (T_LEN * XDIM) + (size_t)t * XDIM + 4 * k4);
        xs[b][4 * k4 + 0] = v.x; xs[b][4 * k4 + 1] = v.y;
        xs[b][4 * k4 + 2] = v.z; xs[b][4 * k4 + 3] = v.w;
    }
    for (int i = tid; i < PG_COLS * 64 * 4; i += 256) {
        int q = i & 3, k = (i >> 2) & 63, c = i >> 8;
        ws[i] = w_ih[(q * HID + colbase + c) * XDIM + k];
    }
    __syncthreads();

    const int b  = tid & 63;
    const int cg = tid >> 6;
    unsigned long long acc01[8], acc23[8];
    #pragma unroll
    for (int c8 = 0; c8 < 8; ++c8) {
        int col = colbase + cg * 8 + c8;
        acc01[c8] = pack2_(bias[0 * HID + col], bias[1 * HID + col]);
        acc23[c8] = pack2_(bias[2 * HID + col], bias[3 * HID + col]);
    }
    #pragma unroll 4
    for (int k = 0; k < 64; ++k) {
        unsigned long long xv = dup2_(xs[b][k]);
        #pragma unroll
        for (int c8 = 0; c8 < 8; ++c8) {
            ulonglong2 w = *(ulonglong2*)&ws[((cg * 8 + c8) * 64 + k) * 4];
            acc01[c8] = fma2_(w.x, xv, acc01[c8]);
            acc23[c8] = fma2_(w.y, xv, acc23[c8]);
        }
    }
    #pragma unroll
    for (int c8 = 0; c8 < 8; ++c8) {
        int col = colbase + cg * 8 + c8;
        float4 o;
        unpack2_(acc01[c8], o.x, o.y);
        unpack2_(acc23[c8], o.z, o.w);
        g_xz[((size_t)t * HID + col) * BATCH + b] = o;
    }
}

// ---------------------------------------------------------------------------
// Persistent LSTM, tagged dataflow with FUSED consume-in-GEMV.
//   CTA (s,beta): cols [4s,4s+4), batches [32beta,32beta+32).
//   warp w: col 4s+(w&3), K-quarter (w>>2). Each warp loads its own tagged h
//   directly from L2 in 8 groups of 8 (depth-2 prefetch), FMAs each group in
//   fixed order once valid. No smem staging, no CTA-wide sync in the loop.
//   part double-buffered by t&1 (WAR safe at depth 2 via the tag chain).
// ---------------------------------------------------------------------------
__global__ void __launch_bounds__(NTHR, 1) lstm_kernel(
    const float* __restrict__ w_hh, float* __restrict__ out)
{
    extern __shared__ __align__(16) float smem[];
    float* wsm = smem;                                   // [4c][256k][4g] 16KB
    ulonglong2* part = (ulonglong2*)(smem + 4 * KH * 4); // [2][3][4c][32l] 12KB
    __shared__ unsigned sh_epoch;

    const int tid   = threadIdx.x;
    const int warp  = tid >> 5;
    const int lane  = tid & 31;
    const int colw  = warp & 3;
    const int kq    = warp >> 2;          // 0..3
    const int s     = blockIdx.x & 63;
    const int beta  = blockIdx.x >> 6;
    const int col   = 4 * s + colw;
    const int b     = 32 * beta + lane;
    const bool owner = (kq == 0);

    if (tid == 0) sh_epoch = atomicAdd(&g_epoch, 1u) >> 7;   // /NCTA -> replay id

    // Recurrent weights: wsm[((colw*256 + k)*4) + q], gate order i,f,g,o
    for (int idx = tid; idx < 4 * KH * 4; idx += NTHR) {
        int q  = idx & 3;
        int kk = (idx >> 2) & 255;
        int cw = idx >> 10;
        wsm[idx] = w_hh[(q * HID + 4 * s + cw) * HID + kk];
    }
    __syncthreads();
    const unsigned epoch = sh_epoch;
    const unsigned tag0  = epoch * (unsigned)(T_LEN + 1) + 1u;  // tag(h_t)=tag0+t

    float c_reg = 0.0f;
    float4 xz = make_float4(0.f, 0.f, 0.f, 0.f);
    float2* gh2 = &g_h2[0][0][0];
    if (owner) {
        vst2_(gh2 + (size_t)col * BATCH + b, 0.0f, tag0);     // h(0)=0, slot 0
        xz = __ldcg(&g_xz[(size_t)col * BATCH + b]);          // xz(t=0)
    }

    const ulonglong2* wr = (const ulonglong2*)wsm + (colw * KH + kq * KQ);
    const size_t out_base = (size_t)b * (T_LEN * HID) + col;

    for (int t = 0; t < T_LEN; ++t) {
        const unsigned exp = tag0 + (unsigned)t;
        const float2* src = gh2 + (size_t)(t & 1) * (KH * BATCH)
                          + (size_t)(kq * KQ) * BATCH + b;
        ulonglong2* pslot = part + (size_t)(t & 1) * (3 * 4 * 32);

        // Fused consume-GEMV: 8 groups of 8 tagged loads, depth-2 prefetch.
        unsigned long long acc01 = 0ull, acc23 = 0ull;
        float2 v[2][8];
        #pragma unroll
        for (int j = 0; j < 8; ++j) v[0][j] = vld2_(src + j * BATCH);
        #pragma unroll
        for (int j = 0; j < 8; ++j) v[1][j] = vld2_(src + (8 + j) * BATCH);

        #pragma unroll
        for (int g = 0; g < 8; ++g) {
            float2* vg = v[g & 1];
            const float2* sg = src + g * 8 * BATCH;
            // Round-poll this group: check all 8, re-fire only stale (MLP=8)
            bool ok;
            do {
                ok = true;
                #pragma unroll
                for (int j = 0; j < 8; ++j)
                    ok &= (__float_as_uint(vg[j].y) == exp);
                if (!ok) {
                    #pragma unroll
                    for (int j = 0; j < 8; ++j)
                        if (__float_as_uint(vg[j].y) != exp)
                            vg[j] = vld2_(sg + j * BATCH);
                }
            } while (!ok);
            // FMA group g in fixed order (deterministic accumulation)
            #pragma unroll
            for (int j = 0; j < 8; ++j) {
                unsigned long long h2 = dup2_(vg[j].x);
                ulonglong2 w = wr[g * 8 + j];
                acc01 = fma2_(w.x, h2, acc01);
                acc23 = fma2_(w.y, h2, acc23);
            }
            // Prefetch group g+2 into the slot we just consumed
            if (g + 2 < 8) {
                const float2* sn = src + (g + 2) * 8 * BATCH;
                #pragma unroll
                for (int j = 0; j < 8; ++j) vg[j] = vld2_(sn + j * BATCH);
            }
        }

        if (!owner) {
            ulonglong2 pv; pv.x = acc01; pv.y = acc23;
            pslot[((kq - 1) * 4 + colw) * 32 + lane] = pv;
        }
        asm volatile("bar.sync %0, 128;" :: "r"(1 + colw) : "memory");

        if (owner) {
            #pragma unroll
            for (int q = 0; q < 3; ++q) {
                ulonglong2 p = pslot[(q * 4 + colw) * 32 + lane];
                acc01 = add2_(acc01, p.x);
                acc23 = add2_(acc23, p.y);
            }
            acc01 = add2_(acc01, pack2_(xz.x, xz.y));     // + x-part + bias
            acc23 = add2_(acc23, pack2_(xz.z, xz.w));
            float a0, a1, a2, a3;
            unpack2_(acc01, a0, a1);
            unpack2_(acc23, a2, a3);

            const float ig = sigmoidf_(a0);
            const float fg = sigmoidf_(a1);
            const float gg = tanh_fast_(a2);
            const float og = sigmoidf_(a3);
            c_reg = fmaf(fg, c_reg, ig * gg);
            const float h = og * tanh_fast_(c_reg);

            // Publish FIRST (consumers spin on this), then sideband stores.
            vst2_(gh2 + (size_t)((t + 1) & 1) * (KH * BATCH)
                      + (size_t)col * BATCH + b, h, exp + 1u);
            out[out_base + (size_t)t * HID] = h;
            if (t + 1 < T_LEN)
                xz = __ldcg(&g_xz[((size_t)(t + 1) * HID + col) * BATCH + b]);
        }
        // No CTA-wide sync: h exchange and part are both depth-2 buffered;
        // the tag chain (publish(t+1) requires full GEMV(t)) provides WAR
        // ordering at distance 2 for both buffers.
    }
}

// ---------------------------------------------------------------------------
extern "C" void kernel_launch(void* const* d_in, const int* in_sizes, int n_in,
                              void* d_out, int out_size) {
    (void)in_sizes; (void)n_in; (void)out_size;
    const float* x    = (const float*)d_in[0];
    const float* w_ih = (const float*)d_in[1];
    const float* w_hh = (const float*)d_in[2];
    const float* bias = (const float*)d_in[3];
    float* out = (float*)d_out;

    const int pg_smem = (64 * 65 + PG_COLS * 64 * 4) * (int)sizeof(float);
    cudaFuncSetAttribute(xz_gemm_kernel,
                         cudaFuncAttributeMaxDynamicSharedMemorySize, pg_smem);
    const int ls_smem = 4 * KH * 4 * (int)sizeof(float)
                        + 2 * 3 * 4 * 32 * (int)sizeof(ulonglong2);  // 16+12 KB
    cudaFuncSetAttribute(lstm_kernel,
                         cudaFuncAttributeMaxDynamicSharedMemorySize, ls_smem);

    dim3 pg_grid(HID / PG_COLS, T_LEN);
    xz_gemm_kernel<<<pg_grid, 256, pg_smem>>>(x, w_ih, bias);
    lstm_kernel<<<NCTA, NTHR, ls_smem>>>(w_hh, out);
}

// round 10
// speedup vs baseline: 1.6126x; 1.6126x over previous
#include <cuda_runtime.h>

#define T_LEN 2048
#define BATCH 64
#define XDIM  64
#define HID   256
#define KH    256            // recurrent K (x part precomputed)
#define KQ    64             // K per quarter-warp

#define NCTA  128            // 2 batch-halves x 64 column-slices
#define NTHR  512            // 16 warps: (warp&3)=column, (warp>>2)=K-quarter

// Static device scratch (no cudaMalloc anywhere)
__device__ float4 g_xz[(size_t)T_LEN * HID * BATCH];   // [t][col][b] pre-activations
// Tagged h exchange: float2 {h, tag} per value, viewed as float4 (2 batches)
__device__ __align__(16) float4 g_h2[2][KH][BATCH / 2];
__device__ unsigned g_epoch;                           // replay epoch counter

// ---------------- packed f32x2 helpers ----------------
__device__ __forceinline__ unsigned long long fma2_(unsigned long long a,
                                                    unsigned long long b,
                                                    unsigned long long c) {
    unsigned long long d;
    asm("fma.rn.f32x2 %0, %1, %2, %3;" : "=l"(d) : "l"(a), "l"(b), "l"(c));
    return d;
}
__device__ __forceinline__ unsigned long long add2_(unsigned long long a,
                                                    unsigned long long b) {
    unsigned long long d;
    asm("add.rn.f32x2 %0, %1, %2;" : "=l"(d) : "l"(a), "l"(b));
    return d;
}
__device__ __forceinline__ unsigned long long dup2_(float x) {
    unsigned long long d;
    asm("mov.b64 %0, {%1, %1};" : "=l"(d) : "r"(__float_as_uint(x)));
    return d;
}
__device__ __forceinline__ unsigned long long pack2_(float lo, float hi) {
    unsigned long long d;
    asm("mov.b64 %0, {%1, %2};" : "=l"(d) : "r"(__float_as_uint(lo)), "r"(__float_as_uint(hi)));
    return d;
}
__device__ __forceinline__ void unpack2_(unsigned long long v, float& lo, float& hi) {
    unsigned a, b;
    asm("mov.b64 {%0, %1}, %2;" : "=r"(a), "=r"(b) : "l"(v));
    lo = __uint_as_float(a); hi = __uint_as_float(b);
}
__device__ __forceinline__ float sigmoidf_(float x) {
    return 1.0f / (1.0f + __expf(-x));
}
__device__ __forceinline__ float tanh_fast_(float x) {   // 2*sigmoid(2x)-1
    return __fmaf_rn(2.0f, 1.0f / (1.0f + __expf(-2.0f * x)), -1.0f);
}

// Volatile 16B load (2 tagged h values); never hoisted/cached
__device__ __forceinline__ float4 vld4_(const float4* p) {
    float4 v;
    asm volatile("ld.volatile.global.v4.f32 {%0,%1,%2,%3}, [%4];"
                 : "=f"(v.x), "=f"(v.y), "=f"(v.z), "=f"(v.w) : "l"(p));
    return v;
}
// Publish one tagged h value (8B single transaction -> no tearing)
__device__ __forceinline__ void vst2_(float2* p, float h, unsigned tag) {
    asm volatile("st.volatile.global.v2.f32 [%0], {%1,%2};"
                 :: "l"(p), "f"(h), "f"(__uint_as_float(tag)) : "memory");
}

// ---------------------------------------------------------------------------
// Pre-kernel: g_xz[t][col][b] = bias + x[b,t,:] . w_ih[4 gate rows of col, :]
// ---------------------------------------------------------------------------
#define PG_COLS 32
__global__ void __launch_bounds__(256) xz_gemm_kernel(
    const float* __restrict__ x, const float* __restrict__ w_ih,
    const float* __restrict__ bias)
{
    extern __shared__ float ps[];
    float (*xs)[65] = (float(*)[65])ps;          // [b][k], padded
    float* ws = ps + 64 * 65;                    // [c][k][q]

    const int t       = blockIdx.y;
    const int colbase = blockIdx.x * PG_COLS;
    const int tid     = threadIdx.x;

    for (int i = tid; i < 64 * 16; i += 256) {
        int b = i >> 4, k4 = i & 15;
        float4 v = *(const float4*)(x + (size_t)b * (T_LEN * XDIM) + (size_t)t * XDIM + 4 * k4);
        xs[b][4 * k4 + 0] = v.x; xs[b][4 * k4 + 1] = v.y;
        xs[b][4 * k4 + 2] = v.z; xs[b][4 * k4 + 3] = v.w;
    }
    for (int i = tid; i < PG_COLS * 64 * 4; i += 256) {
        int q = i & 3, k = (i >> 2) & 63, c = i >> 8;
        ws[i] = w_ih[(q * HID + colbase + c) * XDIM + k];
    }
    __syncthreads();

    const int b  = tid & 63;
    const int cg = tid >> 6;
    unsigned long long acc01[8], acc23[8];
    #pragma unroll
    for (int c8 = 0; c8 < 8; ++c8) {
        int col = colbase + cg * 8 + c8;
        acc01[c8] = pack2_(bias[0 * HID + col], bias[1 * HID + col]);
        acc23[c8] = pack2_(bias[2 * HID + col], bias[3 * HID + col]);
    }
    #pragma unroll 4
    for (int k = 0; k < 64; ++k) {
        unsigned long long xv = dup2_(xs[b][k]);
        #pragma unroll
        for (int c8 = 0; c8 < 8; ++c8) {
            ulonglong2 w = *(ulonglong2*)&ws[((cg * 8 + c8) * 64 + k) * 4];
            acc01[c8] = fma2_(w.x, xv, acc01[c8]);
            acc23[c8] = fma2_(w.y, xv, acc23[c8]);
        }
    }
    #pragma unroll
    for (int c8 = 0; c8 < 8; ++c8) {
        int col = colbase + cg * 8 + c8;
        float4 o;
        unpack2_(acc01[c8], o.x, o.y);
        unpack2_(acc23[c8], o.z, o.w);
        g_xz[((size_t)t * HID + col) * BATCH + b] = o;
    }
}

// ---------------------------------------------------------------------------
// Persistent LSTM, tagged dataflow, per-QUARTER decoupled staging.
//   CTA (s,beta): cols [4s,4s+4), batches [32beta,32beta+32).
//   warp w: col 4s+(w&3), K-quarter (w>>2).
//   Quarter group q = warps {4q..4q+3} stages ONLY k in [64q,64q+64) and
//   syncs with named barrier (5+q, 128). Col group c = warps {c,c+4,c+8,c+12}
//   combines partials via named barrier (1+c, 128). NO CTA-wide sync in loop.
//   hs and part double-buffered by t&1; WAR at distance 2 ordered by the
//   shared barriers at t+1 (each pair of racing threads shares one of them).
// ---------------------------------------------------------------------------
__global__ void __launch_bounds__(NTHR, 1) lstm_kernel(
    const float* __restrict__ w_hh, float* __restrict__ out)
{
    extern __shared__ __align__(16) float smem[];
    float* wsm = smem;                                     // [4c][256k][4g] 16KB
    float* hs  = smem + 4 * KH * 4;                        // [2][256k][32b] 64KB
    ulonglong2* part = (ulonglong2*)(hs + 2 * KH * 32);    // [2][3][4c][32l] 12KB
    __shared__ unsigned sh_epoch;

    const int tid   = threadIdx.x;
    const int warp  = tid >> 5;
    const int lane  = tid & 31;
    const int colw  = warp & 3;
    const int kq    = warp >> 2;          // 0..3
    const int gtid  = tid & 127;          // tid within quarter group (warps 4q..4q+3)
    const int s     = blockIdx.x & 63;
    const int beta  = blockIdx.x >> 6;
    const int col   = 4 * s + colw;
    const int b     = 32 * beta + lane;
    const bool owner = (kq == 0);

    if (tid == 0) sh_epoch = atomicAdd(&g_epoch, 1u) >> 7;   // /NCTA -> replay id

    // Recurrent weights: wsm[((colw*256 + k)*4) + q], gate order i,f,g,o
    for (int idx = tid; idx < 4 * KH * 4; idx += NTHR) {
        int q  = idx & 3;
        int kk = (idx >> 2) & 255;
        int cw = idx >> 10;
        wsm[idx] = w_hh[(q * HID + 4 * s + cw) * HID + kk];
    }
    __syncthreads();
    const unsigned epoch = sh_epoch;
    const unsigned tag0  = epoch * (unsigned)(T_LEN + 1) + 1u;  // tag(h_t)=tag0+t

    float c_reg = 0.0f;
    float4 xz = make_float4(0.f, 0.f, 0.f, 0.f);
    float2* gh2 = (float2*)g_h2;
    if (owner) {
        vst2_(gh2 + ((size_t)0 * KH + col) * BATCH + b, 0.0f, tag0);  // h(0)=0
        xz = __ldcg(&g_xz[(size_t)col * BATCH + b]);                  // xz(t=0)
    }

    const ulonglong2* wr = (const ulonglong2*)wsm + (colw * KH + kq * KQ);
    const size_t out_base = (size_t)b * (T_LEN * HID) + col;
    const float4* ghv_base = &g_h2[0][0][0];

    // Per-thread staging coordinates within THIS quarter:
    // quarter = KQ x 32 values = 1024 float4 / 128 threads = 8 each
    int kk_[8], bp_[8];
    #pragma unroll
    for (int i = 0; i < 8; ++i) {
        int idx = gtid + i * 128;              // 0..1023
        kk_[i] = kq * KQ + (idx >> 4);         // global k
        bp_[i] = idx & 15;                     // batch-pair within half
    }

    for (int t = 0; t < T_LEN; ++t) {
        const unsigned exp = tag0 + (unsigned)t;
        const float4* src = ghv_base + (size_t)(t & 1) * KH * (BATCH / 2)
                          + 16 * beta;
        float* hbuf = hs + (size_t)(t & 1) * (KH * 32);
        ulonglong2* pslot = part + (size_t)(t & 1) * (3 * 4 * 32);

        // Round-based tagged staging of OUR quarter: fire all 8, re-fire
        // pending together (MLP=8/round) until all tags match.
        float4 v[8];
        #pragma unroll
        for (int i = 0; i < 8; ++i) v[i] = vld4_(src + kk_[i] * (BATCH / 2) + bp_[i]);
        unsigned pend = 0xffu;
        while (true) {
            #pragma unroll
            for (int i = 0; i < 8; ++i) {
                if (pend & (1u << i)) {
                    if (__float_as_uint(v[i].y) == exp &&
                        __float_as_uint(v[i].w) == exp) {
                        *(float2*)&hbuf[kk_[i] * 32 + 2 * bp_[i]] =
                            make_float2(v[i].x, v[i].z);
                        pend &= ~(1u << i);
                    }
                }
            }
            if (!pend) break;
            #pragma unroll
            for (int i = 0; i < 8; ++i)
                if (pend & (1u << i))
                    v[i] = vld4_(src + kk_[i] * (BATCH / 2) + bp_[i]);
        }
        // Quarter-group barrier: our 128 threads (the only readers of this
        // k-range) see the fully staged quarter.
        asm volatile("bar.sync %0, 128;" :: "r"(5 + kq) : "memory");

        // K-quarter GEMV: per k = LDS.32 + LDS.128 + dup + 2 FFMA2
        const float* xb = hbuf + kq * KQ * 32 + lane;
        unsigned long long acc01 = 0ull, acc23 = 0ull;
        #pragma unroll 8
        for (int k = 0; k < KQ; ++k) {
            unsigned long long hv2 = dup2_(xb[k * 32]);
            ulonglong2 w = wr[k];
            acc01 = fma2_(w.x, hv2, acc01);
            acc23 = fma2_(w.y, hv2, acc23);
        }

        if (!owner) {
            ulonglong2 pv; pv.x = acc01; pv.y = acc23;
            pslot[((kq - 1) * 4 + colw) * 32 + lane] = pv;
        }
        asm volatile("bar.sync %0, 128;" :: "r"(1 + colw) : "memory");

        if (owner) {
            #pragma unroll
            for (int q = 0; q < 3; ++q) {
                ulonglong2 p = pslot[(q * 4 + colw) * 32 + lane];
                acc01 = add2_(acc01, p.x);
                acc23 = add2_(acc23, p.y);
            }
            acc01 = add2_(acc01, pack2_(xz.x, xz.y));     // + x-part + bias
            acc23 = add2_(acc23, pack2_(xz.z, xz.w));
            float a0, a1, a2, a3;
            unpack2_(acc01, a0, a1);
            unpack2_(acc23, a2, a3);

            const float ig = sigmoidf_(a0);
            const float fg = sigmoidf_(a1);
            const float gg = tanh_fast_(a2);
            const float og = sigmoidf_(a3);
            c_reg = fmaf(fg, c_reg, ig * gg);
            const float h = og * tanh_fast_(c_reg);

            // Publish FIRST (consumers spin on this), then sideband stores.
            vst2_(gh2 + ((size_t)((t + 1) & 1) * KH + col) * BATCH + b,
                  h, exp + 1u);
            out[out_base + (size_t)t * HID] = h;
            if (t + 1 < T_LEN)
                xz = __ldcg(&g_xz[((size_t)(t + 1) * HID + col) * BATCH + b]);
        }
        // No CTA-wide sync: hs (per-quarter, depth-2) ordered by quarter bar
        // at t+1; part (per-col, depth-2) ordered by col bar at t+1; the h
        // exchange is depth-2 ordered by the tag chain itself.
    }
}

// ---------------------------------------------------------------------------
extern "C" void kernel_launch(void* const* d_in, const int* in_sizes, int n_in,
                              void* d_out, int out_size) {
    (void)in_sizes; (void)n_in; (void)out_size;
    const float* x    = (const float*)d_in[0];
    const float* w_ih = (const float*)d_in[1];
    const float* w_hh = (const float*)d_in[2];
    const float* bias = (const float*)d_in[3];
    float* out = (float*)d_out;

    const int pg_smem = (64 * 65 + PG_COLS * 64 * 4) * (int)sizeof(float);
    cudaFuncSetAttribute(xz_gemm_kernel,
                         cudaFuncAttributeMaxDynamicSharedMemorySize, pg_smem);
    const int ls_smem = (4 * KH * 4 + 2 * KH * 32) * (int)sizeof(float)
                        + 2 * 3 * 4 * 32 * (int)sizeof(ulonglong2); // 16+64+12 KB
    cudaFuncSetAttribute(lstm_kernel,
                         cudaFuncAttributeMaxDynamicSharedMemorySize, ls_smem);

    dim3 pg_grid(HID / PG_COLS, T_LEN);
    xz_gemm_kernel<<<pg_grid, 256, pg_smem>>>(x, w_ih, bias);
    lstm_kernel<<<NCTA, NTHR, ls_smem>>>(w_hh, out);
}

// round 11
// speedup vs baseline: 1.6833x; 1.0439x over previous
#include <cuda_runtime.h>

#define T_LEN 2048
#define BATCH 64
#define XDIM  64
#define HID   256
#define KH    256            // recurrent K (x part precomputed)
#define KQ    64             // K per quarter-group (staging granularity)
#define KW    16             // K per warp (GEMV granularity)

#define NCTA  128            // 2 batch-halves x 64 column-slices
#define NTHR  512            // 16 warps, warp w = k-slice [16w,16w+16)

// Static device scratch (no cudaMalloc anywhere)
__device__ float4 g_xz[(size_t)T_LEN * HID * BATCH];   // [t][col][b] pre-activations
// Tagged h exchange: float2 {h, tag} per value, viewed as float4 (2 batches)
__device__ __align__(16) float4 g_h2[2][KH][BATCH / 2];
__device__ unsigned g_epoch;                           // replay epoch counter

// ---------------- packed f32x2 helpers ----------------
__device__ __forceinline__ unsigned long long fma2_(unsigned long long a,
                                                    unsigned long long b,
                                                    unsigned long long c) {
    unsigned long long d;
    asm("fma.rn.f32x2 %0, %1, %2, %3;" : "=l"(d) : "l"(a), "l"(b), "l"(c));
    return d;
}
__device__ __forceinline__ unsigned long long add2_(unsigned long long a,
                                                    unsigned long long b) {
    unsigned long long d;
    asm("add.rn.f32x2 %0, %1, %2;" : "=l"(d) : "l"(a), "l"(b));
    return d;
}
__device__ __forceinline__ unsigned long long dup2_(float x) {
    unsigned long long d;
    asm("mov.b64 %0, {%1, %1};" : "=l"(d) : "r"(__float_as_uint(x)));
    return d;
}
__device__ __forceinline__ unsigned long long pack2_(float lo, float hi) {
    unsigned long long d;
    asm("mov.b64 %0, {%1, %2};" : "=l"(d) : "r"(__float_as_uint(lo)), "r"(__float_as_uint(hi)));
    return d;
}
__device__ __forceinline__ void unpack2_(unsigned long long v, float& lo, float& hi) {
    unsigned a, b;
    asm("mov.b64 {%0, %1}, %2;" : "=r"(a), "=r"(b) : "l"(v));
    lo = __uint_as_float(a); hi = __uint_as_float(b);
}
__device__ __forceinline__ float sigmoidf_(float x) {
    return 1.0f / (1.0f + __expf(-x));
}
__device__ __forceinline__ float tanh_fast_(float x) {   // 2*sigmoid(2x)-1
    return __fmaf_rn(2.0f, 1.0f / (1.0f + __expf(-2.0f * x)), -1.0f);
}

// Volatile 16B load (2 tagged h values); never hoisted/cached
__device__ __forceinline__ float4 vld4_(const float4* p) {
    float4 v;
    asm volatile("ld.volatile.global.v4.f32 {%0,%1,%2,%3}, [%4];"
                 : "=f"(v.x), "=f"(v.y), "=f"(v.z), "=f"(v.w) : "l"(p));
    return v;
}
// Publish one tagged h value (8B single transaction -> no tearing)
__device__ __forceinline__ void vst2_(float2* p, float h, unsigned tag) {
    asm volatile("st.volatile.global.v2.f32 [%0], {%1,%2};"
                 :: "l"(p), "f"(h), "f"(__uint_as_float(tag)) : "memory");
}

// ---------------------------------------------------------------------------
// Pre-kernel: g_xz[t][col][b] = bias + x[b,t,:] . w_ih[4 gate rows of col, :]
// ---------------------------------------------------------------------------
#define PG_COLS 32
__global__ void __launch_bounds__(256) xz_gemm_kernel(
    const float* __restrict__ x, const float* __restrict__ w_ih,
    const float* __restrict__ bias)
{
    extern __shared__ float ps[];
    float (*xs)[65] = (float(*)[65])ps;          // [b][k], padded
    float* ws = ps + 64 * 65;                    // [c][k][q]

    const int t       = blockIdx.y;
    const int colbase = blockIdx.x * PG_COLS;
    const int tid     = threadIdx.x;

    for (int i = tid; i < 64 * 16; i += 256) {
        int b = i >> 4, k4 = i & 15;
        float4 v = *(const float4*)(x + (size_t)b * (T_LEN * XDIM) + (size_t)t * XDIM + 4 * k4);
        xs[b][4 * k4 + 0] = v.x; xs[b][4 * k4 + 1] = v.y;
        xs[b][4 * k4 + 2] = v.z; xs[b][4 * k4 + 3] = v.w;
    }
    for (int i = tid; i < PG_COLS * 64 * 4; i += 256) {
        int q = i & 3, k = (i >> 2) & 63, c = i >> 8;
        ws[i] = w_ih[(q * HID + colbase + c) * XDIM + k];
    }
    __syncthreads();

    const int b  = tid & 63;
    const int cg = tid >> 6;
    unsigned long long acc01[8], acc23[8];
    #pragma unroll
    for (int c8 = 0; c8 < 8; ++c8) {
        int col = colbase + cg * 8 + c8;
        acc01[c8] = pack2_(bias[0 * HID + col], bias[1 * HID + col]);
        acc23[c8] = pack2_(bias[2 * HID + col], bias[3 * HID + col]);
    }
    #pragma unroll 4
    for (int k = 0; k < 64; ++k) {
        unsigned long long xv = dup2_(xs[b][k]);
        #pragma unroll
        for (int c8 = 0; c8 < 8; ++c8) {
            ulonglong2 w = *(ulonglong2*)&ws[((cg * 8 + c8) * 64 + k) * 4];
            acc01[c8] = fma2_(w.x, xv, acc01[c8]);
            acc23[c8] = fma2_(w.y, xv, acc23[c8]);
        }
    }
    #pragma unroll
    for (int c8 = 0; c8 < 8; ++c8) {
        int col = colbase + cg * 8 + c8;
        float4 o;
        unpack2_(acc01[c8], o.x, o.y);
        unpack2_(acc23[c8], o.z, o.w);
        g_xz[((size_t)t * HID + col) * BATCH + b] = o;
    }
}

// ---------------------------------------------------------------------------
// Persistent LSTM, tagged dataflow, k-sliced GEMV + 2-stage reduce.
//   CTA (s,beta): cols [4s,4s+4), batches [32beta,32beta+32).
//   Staging: quarter group q = warps {4q..4q+3} stages k in [64q,64q+64),
//            named barrier (5+q, 128).
//   GEMV: warp w handles k-slice [16w,16w+16) x ALL 4 cols x 4 gates
//         (1 act LDS.32 amortized over 4 cols -> 4x fewer act wavefronts).
//   Reduce stage 1 (after quarter bar): warp 4q+c sums its group's 4 partials
//         for col c -> part2[q][c].
//   Reduce stage 2 (after col bar 1+c, warps {c,c+4,c+8,c+12}): owner warp c
//         (q=0) sums 4 quarter partials + xz, pointwise, publish.
//   All buffers (hs, part1, part2, h exchange) depth-2 by t&1; WAR at
//   distance 2 ordered by the shared named barriers at t+1.
// ---------------------------------------------------------------------------
__global__ void __launch_bounds__(NTHR, 1) lstm_kernel(
    const float* __restrict__ w_hh, float* __restrict__ out)
{
    extern __shared__ __align__(16) float smem[];
    float* wsm = smem;                                     // [256k][4c][4g] 16KB
    float* hs  = smem + 4 * KH * 4;                        // [2][256k][32b] 64KB
    ulonglong2* part1 = (ulonglong2*)(hs + 2 * KH * 32);   // [2][16w][4c][32l] 64KB
    ulonglong2* part2 = part1 + 2 * 16 * 4 * 32;           // [2][4q][4c][32l] 16KB
    __shared__ unsigned sh_epoch;

    const int tid   = threadIdx.x;
    const int warp  = tid >> 5;
    const int lane  = tid & 31;
    const int cw    = warp & 3;           // col duty within groups
    const int kq    = warp >> 2;          // quarter group 0..3
    const int gtid  = tid & 127;          // tid within quarter group
    const int s     = blockIdx.x & 63;
    const int beta  = blockIdx.x >> 6;
    const int col   = 4 * s + cw;         // col for reduce/owner duties
    const int b     = 32 * beta + lane;
    const bool owner = (kq == 0);

    if (tid == 0) sh_epoch = atomicAdd(&g_epoch, 1u) >> 7;   // /NCTA -> replay id

    // Weights: wsm[((k*4 + c)*4) + q] = w_hh[q*HID + 4s+c][k], gates i,f,g,o
    for (int idx = tid; idx < 4 * KH * 4; idx += NTHR) {
        int q = idx & 3, c = (idx >> 2) & 3, k = idx >> 4;
        wsm[idx] = w_hh[(q * HID + 4 * s + c) * HID + k];
    }
    __syncthreads();
    const unsigned epoch = sh_epoch;
    const unsigned tag0  = epoch * (unsigned)(T_LEN + 1) + 1u;  // tag(h_t)=tag0+t

    float c_reg = 0.0f;
    float4 xz = make_float4(0.f, 0.f, 0.f, 0.f);
    float2* gh2 = (float2*)g_h2;
    if (owner) {
        vst2_(gh2 + ((size_t)0 * KH + col) * BATCH + b, 0.0f, tag0);  // h(0)=0
        xz = __ldcg(&g_xz[(size_t)col * BATCH + b]);                  // xz(t=0)
    }

    const size_t out_base = (size_t)b * (T_LEN * HID) + col;
    const float4* ghv_base = &g_h2[0][0][0];
    const ulonglong2* wk = (const ulonglong2*)wsm + warp * KW * 4;    // [k16][c4]

    // Staging coordinates within this quarter: 1024 float4 / 128 thr = 8 each
    int kk_[8], bp_[8];
    #pragma unroll
    for (int i = 0; i < 8; ++i) {
        int idx = gtid + i * 128;              // 0..1023
        kk_[i] = kq * KQ + (idx >> 4);         // global k
        bp_[i] = idx & 15;                     // batch-pair within half
    }

    for (int t = 0; t < T_LEN; ++t) {
        const unsigned exp = tag0 + (unsigned)t;
        const int buf = t & 1;
        const float4* src = ghv_base + (size_t)buf * KH * (BATCH / 2) + 16 * beta;
        float* hbuf = hs + (size_t)buf * (KH * 32);
        ulonglong2* p1 = part1 + (size_t)buf * (16 * 4 * 32);
        ulonglong2* p2 = part2 + (size_t)buf * (4 * 4 * 32);

        // Round-based tagged staging of OUR quarter (MLP=8 per round).
        float4 v[8];
        #pragma unroll
        for (int i = 0; i < 8; ++i) v[i] = vld4_(src + kk_[i] * (BATCH / 2) + bp_[i]);
        unsigned pend = 0xffu;
        while (true) {
            #pragma unroll
            for (int i = 0; i < 8; ++i) {
                if (pend & (1u << i)) {
                    if (__float_as_uint(v[i].y) == exp &&
                        __float_as_uint(v[i].w) == exp) {
                        *(float2*)&hbuf[kk_[i] * 32 + 2 * bp_[i]] =
                            make_float2(v[i].x, v[i].z);
                        pend &= ~(1u << i);
                    }
                }
            }
            if (!pend) break;
            #pragma unroll
            for (int i = 0; i < 8; ++i)
                if (pend & (1u << i))
                    v[i] = vld4_(src + kk_[i] * (BATCH / 2) + bp_[i]);
        }
        asm volatile("bar.sync %0, 128;" :: "r"(5 + kq) : "memory");   // quarter staged

        // GEMV: 16 k, all 4 cols. Per k: 1 act LDS.32 + dup + 4 wgt LDS.128
        // (broadcast) + 8 FFMA2.
        const float* xb = hbuf + warp * KW * 32 + lane;
        unsigned long long a01[4] = {0ull, 0ull, 0ull, 0ull};
        unsigned long long a23[4] = {0ull, 0ull, 0ull, 0ull};
        #pragma unroll
        for (int k = 0; k < KW; ++k) {
            unsigned long long hv2 = dup2_(xb[k * 32]);
            #pragma unroll
            for (int c = 0; c < 4; ++c) {
                ulonglong2 w2 = wk[k * 4 + c];
                a01[c] = fma2_(w2.x, hv2, a01[c]);
                a23[c] = fma2_(w2.y, hv2, a23[c]);
            }
        }
        #pragma unroll
        for (int c = 0; c < 4; ++c) {
            ulonglong2 pv; pv.x = a01[c]; pv.y = a23[c];
            p1[(warp * 4 + c) * 32 + lane] = pv;
        }
        asm volatile("bar.sync %0, 128;" :: "r"(5 + kq) : "memory");   // partials ready

        // Stage-1 reduce: warp 4*kq+cw sums group kq's 4 partials for col cw.
        {
            ulonglong2 r0 = p1[((kq * 4 + 0) * 4 + cw) * 32 + lane];
            ulonglong2 r1 = p1[((kq * 4 + 1) * 4 + cw) * 32 + lane];
            ulonglong2 r2 = p1[((kq * 4 + 2) * 4 + cw) * 32 + lane];
            ulonglong2 r3 = p1[((kq * 4 + 3) * 4 + cw) * 32 + lane];
            ulonglong2 q01;
            q01.x = add2_(add2_(r0.x, r1.x), add2_(r2.x, r3.x));
            q01.y = add2_(add2_(r0.y, r1.y), add2_(r2.y, r3.y));
            p2[(kq * 4 + cw) * 32 + lane] = q01;
        }
        asm volatile("bar.sync %0, 128;" :: "r"(1 + cw) : "memory");   // col group

        if (owner) {   // warp cw, quarter 0: final combine + pointwise + publish
            ulonglong2 r0 = p2[(0 * 4 + cw) * 32 + lane];
            ulonglong2 r1 = p2[(1 * 4 + cw) * 32 + lane];
            ulonglong2 r2 = p2[(2 * 4 + cw) * 32 + lane];
            ulonglong2 r3 = p2[(3 * 4 + cw) * 32 + lane];
            unsigned long long acc01 =
                add2_(add2_(r0.x, r1.x), add2_(r2.x, r3.x));
            unsigned long long acc23 =
                add2_(add2_(r0.y, r1.y), add2_(r2.y, r3.y));
            acc01 = add2_(acc01, pack2_(xz.x, xz.y));     // + x-part + bias
            acc23 = add2_(acc23, pack2_(xz.z, xz.w));
            float a0, a1, a2, a3;
            unpack2_(acc01, a0, a1);
            unpack2_(acc23, a2, a3);

            const float ig = sigmoidf_(a0);
            const float fg = sigmoidf_(a1);
            const float gg = tanh_fast_(a2);
            const float og = sigmoidf_(a3);
            c_reg = fmaf(fg, c_reg, ig * gg);
            const float h = og * tanh_fast_(c_reg);

            // Publish FIRST (consumers spin on this), then sideband stores.
            vst2_(gh2 + ((size_t)((t + 1) & 1) * KH + col) * BATCH + b,
                  h, exp + 1u);
            out[out_base + (size_t)t * HID] = h;
            if (t + 1 < T_LEN)
                xz = __ldcg(&g_xz[((size_t)(t + 1) * HID + col) * BATCH + b]);
        }
        // No CTA-wide sync. WAR at distance 2 for hs/part1 (quarter bars),
        // part2 (col bars), h exchange (tag chain) — see header comment.
    }
}

// ---------------------------------------------------------------------------
extern "C" void kernel_launch(void* const* d_in, const int* in_sizes, int n_in,
                              void* d_out, int out_size) {
    (void)in_sizes; (void)n_in; (void)out_size;
    const float* x    = (const float*)d_in[0];
    const float* w_ih = (const float*)d_in[1];
    const float* w_hh = (const float*)d_in[2];
    const float* bias = (const float*)d_in[3];
    float* out = (float*)d_out;

    const int pg_smem = (64 * 65 + PG_COLS * 64 * 4) * (int)sizeof(float);
    cudaFuncSetAttribute(xz_gemm_kernel,
                         cudaFuncAttributeMaxDynamicSharedMemorySize, pg_smem);
    const int ls_smem = (4 * KH * 4 + 2 * KH * 32) * (int)sizeof(float)
                        + (2 * 16 * 4 * 32 + 2 * 4 * 4 * 32)
                          * (int)sizeof(ulonglong2);   // 16+64+64+16 = 160 KB
    cudaFuncSetAttribute(lstm_kernel,
                         cudaFuncAttributeMaxDynamicSharedMemorySize, ls_smem);

    dim3 pg_grid(HID / PG_COLS, T_LEN);
    xz_gemm_kernel<<<pg_grid, 256, pg_smem>>>(x, w_ih, bias);
    lstm_kernel<<<NCTA, NTHR, ls_smem>>>(w_hh, out);
}

// round 12
// speedup vs baseline: 1.9276x; 1.1451x over previous
#include <cuda_runtime.h>

#define T_LEN 2048
#define BATCH 64
#define XDIM  64
#define HID   256
#define KH    256            // recurrent K (x part precomputed)
#define KW    16             // K per warp (GEMV granularity)

#define NCTA  128            // 2 batch-halves x 64 column-slices
#define NTHR  512            // 16 warps, warp w = k-slice [16w,16w+16)

// Static device scratch (no cudaMalloc anywhere)
__device__ float4 g_xz[(size_t)T_LEN * HID * BATCH];   // [t][col][b] pre-activations
__device__ __align__(16) float2 g_h2[2][KH][BATCH];    // tagged h: {h, tag}
__device__ unsigned g_epoch;                           // replay epoch counter

// ---------------- packed f32x2 helpers ----------------
__device__ __forceinline__ unsigned long long fma2_(unsigned long long a,
                                                    unsigned long long b,
                                                    unsigned long long c) {
    unsigned long long d;
    asm("fma.rn.f32x2 %0, %1, %2, %3;" : "=l"(d) : "l"(a), "l"(b), "l"(c));
    return d;
}
__device__ __forceinline__ unsigned long long add2_(unsigned long long a,
                                                    unsigned long long b) {
    unsigned long long d;
    asm("add.rn.f32x2 %0, %1, %2;" : "=l"(d) : "l"(a), "l"(b));
    return d;
}
__device__ __forceinline__ unsigned long long dup2_(float x) {
    unsigned long long d;
    asm("mov.b64 %0, {%1, %1};" : "=l"(d) : "r"(__float_as_uint(x)));
    return d;
}
__device__ __forceinline__ unsigned long long pack2_(float lo, float hi) {
    unsigned long long d;
    asm("mov.b64 %0, {%1, %2};" : "=l"(d) : "r"(__float_as_uint(lo)), "r"(__float_as_uint(hi)));
    return d;
}
__device__ __forceinline__ void unpack2_(unsigned long long v, float& lo, float& hi) {
    unsigned a, b;
    asm("mov.b64 {%0, %1}, %2;" : "=r"(a), "=r"(b) : "l"(v));
    lo = __uint_as_float(a); hi = __uint_as_float(b);
}
__device__ __forceinline__ float sigmoidf_(float x) {
    return 1.0f / (1.0f + __expf(-x));
}
__device__ __forceinline__ float tanh_fast_(float x) {   // 2*sigmoid(2x)-1
    return __fmaf_rn(2.0f, 1.0f / (1.0f + __expf(-2.0f * x)), -1.0f);
}

// Volatile tagged 8B load/store (single transaction -> no tearing)
__device__ __forceinline__ float2 vld2_(const float2* p) {
    float2 v;
    asm volatile("ld.volatile.global.v2.f32 {%0,%1}, [%2];"
                 : "=f"(v.x), "=f"(v.y) : "l"(p));
    return v;
}
__device__ __forceinline__ void vst2_(float2* p, float h, unsigned tag) {
    asm volatile("st.volatile.global.v2.f32 [%0], {%1,%2};"
                 :: "l"(p), "f"(h), "f"(__uint_as_float(tag)) : "memory");
}

// ---------------------------------------------------------------------------
// Pre-kernel: g_xz[t][col][b] = bias + x[b,t,:] . w_ih[4 gate rows of col, :]
// ---------------------------------------------------------------------------
#define PG_COLS 32
__global__ void __launch_bounds__(256) xz_gemm_kernel(
    const float* __restrict__ x, const float* __restrict__ w_ih,
    const float* __restrict__ bias)
{
    extern __shared__ float ps[];
    float (*xs)[65] = (float(*)[65])ps;          // [b][k], padded
    float* ws = ps + 64 * 65;                    // [c][k][q]

    const int t       = blockIdx.y;
    const int colbase = blockIdx.x * PG_COLS;
    const int tid     = threadIdx.x;

    for (int i = tid; i < 64 * 16; i += 256) {
        int b = i >> 4, k4 = i & 15;
        float4 v = *(const float4*)(x + (size_t)b * (T_LEN * XDIM) + (size_t)t * XDIM + 4 * k4);
        xs[b][4 * k4 + 0] = v.x; xs[b][4 * k4 + 1] = v.y;
        xs[b][4 * k4 + 2] = v.z; xs[b][4 * k4 + 3] = v.w;
    }
    for (int i = tid; i < PG_COLS * 64 * 4; i += 256) {
        int q = i & 3, k = (i >> 2) & 63, c = i >> 8;
        ws[i] = w_ih[(q * HID + colbase + c) * XDIM + k];
    }
    __syncthreads();

    const int b  = tid & 63;
    const int cg = tid >> 6;
    unsigned long long acc01[8], acc23[8];
    #pragma unroll
    for (int c8 = 0; c8 < 8; ++c8) {
        int col = colbase + cg * 8 + c8;
        acc01[c8] = pack2_(bias[0 * HID + col], bias[1 * HID + col]);
        acc23[c8] = pack2_(bias[2 * HID + col], bias[3 * HID + col]);
    }
    #pragma unroll 4
    for (int k = 0; k < 64; ++k) {
        unsigned long long xv = dup2_(xs[b][k]);
        #pragma unroll
        for (int c8 = 0; c8 < 8; ++c8) {
            ulonglong2 w = *(ulonglong2*)&ws[((cg * 8 + c8) * 64 + k) * 4];
            acc01[c8] = fma2_(w.x, xv, acc01[c8]);
            acc23[c8] = fma2_(w.y, xv, acc23[c8]);
        }
    }
    #pragma unroll
    for (int c8 = 0; c8 < 8; ++c8) {
        int col = colbase + cg * 8 + c8;
        float4 o;
        unpack2_(acc01[c8], o.x, o.y);
        unpack2_(acc23[c8], o.z, o.w);
        g_xz[((size_t)t * HID + col) * BATCH + b] = o;
    }
}

// ---------------------------------------------------------------------------
// Persistent LSTM, tagged dataflow: direct-from-L2 k-sliced GEMV (no smem
// act staging) + 2-stage reduce.
//   CTA (s,beta): cols [4s,4s+4), batches [32beta,32beta+32).
//   Warp w: k-slice [16w,16w+16), lane = batch. Each warp loads its own
//   16 tagged h values per step straight from L2 (coalesced 256B per k,
//   MLP=16; stale values re-loaded predicated), then FMAs all 4 cols x
//   4 gates from registers. No other warp touches this k-slice.
//   Reduce 1 (quarter bar 5+kq): warp 4kq+c sums its group's 4 partials.
//   Reduce 2 (col bar 1+c): owner warp c sums 4 quarter partials + xz,
//   pointwise, publish. All smem partial buffers depth-2 by t&1; h-slot
//   WAR at distance 2 ordered by the in-CTA barrier chain + tag chain.
// ---------------------------------------------------------------------------
__global__ void __launch_bounds__(NTHR, 1) lstm_kernel(
    const float* __restrict__ w_hh, float* __restrict__ out)
{
    extern __shared__ __align__(16) float smem[];
    float* wsm = smem;                                     // [256k][4c][4g] 16KB
    ulonglong2* part1 = (ulonglong2*)(smem + 4 * KH * 4);  // [2][16w][4c][32l] 64KB
    ulonglong2* part2 = part1 + 2 * 16 * 4 * 32;           // [2][4q][4c][32l] 16KB
    __shared__ unsigned sh_epoch;

    const int tid   = threadIdx.x;
    const int warp  = tid >> 5;
    const int lane  = tid & 31;
    const int cw    = warp & 3;           // col duty within groups
    const int kq    = warp >> 2;          // quarter group 0..3
    const int s     = blockIdx.x & 63;
    const int beta  = blockIdx.x >> 6;
    const int col   = 4 * s + cw;         // col for reduce/owner duties
    const int b     = 32 * beta + lane;
    const bool owner = (kq == 0);

    if (tid == 0) sh_epoch = atomicAdd(&g_epoch, 1u) >> 7;   // /NCTA -> replay id

    // Weights: wsm[((k*4 + c)*4) + q] = w_hh[q*HID + 4s+c][k], gates i,f,g,o
    for (int idx = tid; idx < 4 * KH * 4; idx += NTHR) {
        int q = idx & 3, c = (idx >> 2) & 3, k = idx >> 4;
        wsm[idx] = w_hh[(q * HID + 4 * s + c) * HID + k];
    }
    __syncthreads();
    const unsigned epoch = sh_epoch;
    const unsigned tag0  = epoch * (unsigned)(T_LEN + 1) + 1u;  // tag(h_t)=tag0+t

    float c_reg = 0.0f;
    float4 xz = make_float4(0.f, 0.f, 0.f, 0.f);
    float2* gh2 = &g_h2[0][0][0];
    if (owner) {
        vst2_(gh2 + (size_t)col * BATCH + b, 0.0f, tag0);     // h(0)=0, slot 0
        xz = __ldcg(&g_xz[(size_t)col * BATCH + b]);          // xz(t=0)
    }

    const size_t out_base = (size_t)b * (T_LEN * HID) + col;
    const ulonglong2* wk = (const ulonglong2*)wsm + warp * KW * 4;   // [k16][c4]
    const float2* src0 = gh2 + (size_t)(warp * KW) * BATCH + b;      // slot 0

    for (int t = 0; t < T_LEN; ++t) {
        const unsigned exp = tag0 + (unsigned)t;
        const int buf = t & 1;
        const float2* src = src0 + (size_t)buf * (KH * BATCH);
        ulonglong2* p1 = part1 + (size_t)buf * (16 * 4 * 32);
        ulonglong2* p2 = part2 + (size_t)buf * (4 * 4 * 32);

        // Direct tagged consume: fire all 16 (MLP=16, coalesced per k),
        // then predicated re-load of stale values per round.
        float2 v[KW];
        #pragma unroll
        for (int i = 0; i < KW; ++i) v[i] = vld2_(src + i * BATCH);
        while (true) {
            bool ok = true;
            #pragma unroll
            for (int i = 0; i < KW; ++i)
                ok &= (__float_as_uint(v[i].y) == exp);
            if (__all_sync(0xffffffffu, ok)) break;
            #pragma unroll
            for (int i = 0; i < KW; ++i)
                if (__float_as_uint(v[i].y) != exp)
                    v[i] = vld2_(src + i * BATCH);
        }

        // GEMV from registers: per k = dup + 4 wgt LDS.128 (bcast) + 8 FFMA2
        unsigned long long a01[4] = {0ull, 0ull, 0ull, 0ull};
        unsigned long long a23[4] = {0ull, 0ull, 0ull, 0ull};
        #pragma unroll
        for (int k = 0; k < KW; ++k) {
            unsigned long long hv2 = dup2_(v[k].x);
            #pragma unroll
            for (int c = 0; c < 4; ++c) {
                ulonglong2 w2 = wk[k * 4 + c];
                a01[c] = fma2_(w2.x, hv2, a01[c]);
                a23[c] = fma2_(w2.y, hv2, a23[c]);
            }
        }
        #pragma unroll
        for (int c = 0; c < 4; ++c) {
            ulonglong2 pv; pv.x = a01[c]; pv.y = a23[c];
            p1[(warp * 4 + c) * 32 + lane] = pv;
        }
        asm volatile("bar.sync %0, 128;" :: "r"(5 + kq) : "memory");   // quarter

        // Stage-1 reduce: warp 4*kq+cw sums group kq's 4 partials for col cw.
        {
            ulonglong2 r0 = p1[((kq * 4 + 0) * 4 + cw) * 32 + lane];
            ulonglong2 r1 = p1[((kq * 4 + 1) * 4 + cw) * 32 + lane];
            ulonglong2 r2 = p1[((kq * 4 + 2) * 4 + cw) * 32 + lane];
            ulonglong2 r3 = p1[((kq * 4 + 3) * 4 + cw) * 32 + lane];
            ulonglong2 q01;
            q01.x = add2_(add2_(r0.x, r1.x), add2_(r2.x, r3.x));
            q01.y = add2_(add2_(r0.y, r1.y), add2_(r2.y, r3.y));
            p2[(kq * 4 + cw) * 32 + lane] = q01;
        }
        asm volatile("bar.sync %0, 128;" :: "r"(1 + cw) : "memory");   // col group

        if (owner) {   // warp cw, quarter 0: final combine + pointwise + publish
            ulonglong2 r0 = p2[(0 * 4 + cw) * 32 + lane];
            ulonglong2 r1 = p2[(1 * 4 + cw) * 32 + lane];
            ulonglong2 r2 = p2[(2 * 4 + cw) * 32 + lane];
            ulonglong2 r3 = p2[(3 * 4 + cw) * 32 + lane];
            unsigned long long acc01 =
                add2_(add2_(r0.x, r1.x), add2_(r2.x, r3.x));
            unsigned long long acc23 =
                add2_(add2_(r0.y, r1.y), add2_(r2.y, r3.y));
            acc01 = add2_(acc01, pack2_(xz.x, xz.y));     // + x-part + bias
            acc23 = add2_(acc23, pack2_(xz.z, xz.w));
            float a0, a1, a2, a3;
            unpack2_(acc01, a0, a1);
            unpack2_(acc23, a2, a3);

            const float ig = sigmoidf_(a0);
            const float fg = sigmoidf_(a1);
            const float gg = tanh_fast_(a2);
            const float og = sigmoidf_(a3);
            c_reg = fmaf(fg, c_reg, ig * gg);
            const float h = og * tanh_fast_(c_reg);

            // Publish FIRST (consumers spin on this), then sideband stores.
            vst2_(gh2 + (size_t)((t + 1) & 1) * (KH * BATCH)
                      + (size_t)col * BATCH + b, h, exp + 1u);
            out[out_base + (size_t)t * HID] = h;
            if (t + 1 < T_LEN)
                xz = __ldcg(&g_xz[((size_t)(t + 1) * HID + col) * BATCH + b]);
        }
        // No CTA-wide sync. p1 WAR(d=2) ordered by quarter bar at t+1;
        // p2 by col bar at t+1; h slots by the cross-CTA tag chain (every
        // CTA's GEMV(t+1) consumes every CTA's tags; publish(t+2) is after
        // the full in-CTA barrier chain of t+1).
    }
}

// ---------------------------------------------------------------------------
extern "C" void kernel_launch(void* const* d_in, const int* in_sizes, int n_in,
                              void* d_out, int out_size) {
    (void)in_sizes; (void)n_in; (void)out_size;
    const float* x    = (const float*)d_in[0];
    const float* w_ih = (const float*)d_in[1];
    const float* w_hh = (const float*)d_in[2];
    const float* bias = (const float*)d_in[3];
    float* out = (float*)d_out;

    const int pg_smem = (64 * 65 + PG_COLS * 64 * 4) * (int)sizeof(float);
    cudaFuncSetAttribute(xz_gemm_kernel,
                         cudaFuncAttributeMaxDynamicSharedMemorySize, pg_smem);
    const int ls_smem = 4 * KH * 4 * (int)sizeof(float)
                        + (2 * 16 * 4 * 32 + 2 * 4 * 4 * 32)
                          * (int)sizeof(ulonglong2);   // 16+64+16 = 96 KB
    cudaFuncSetAttribute(lstm_kernel,
                         cudaFuncAttributeMaxDynamicSharedMemorySize, ls_smem);

    dim3 pg_grid(HID / PG_COLS, T_LEN);
    xz_gemm_kernel<<<pg_grid, 256, pg_smem>>>(x, w_ih, bias);
    lstm_kernel<<<NCTA, NTHR, ls_smem>>>(w_hh, out);
}

// round 13
// speedup vs baseline: 1.9567x; 1.0151x over previous
#include <cuda_runtime.h>

#define T_LEN 2048
#define BATCH 64
#define XDIM  64
#define HID   256
#define KH    256            // recurrent K (x part precomputed)
#define KW    16             // K per warp (GEMV granularity)

#define NCTA  128            // 2 batch-halves x 64 column-slices
#define NTHR  512            // 16 warps, warp w = k-slice [16w,16w+16)

// Static device scratch (no cudaMalloc anywhere)
__device__ float4 g_xz[(size_t)T_LEN * HID * BATCH];   // [t][col][b] pre-activations
__device__ __align__(16) float2 g_h2[2][KH][BATCH];    // tagged h: {h, tag}
__device__ unsigned g_epoch;                           // replay epoch counter

// ---------------- packed f32x2 helpers ----------------
__device__ __forceinline__ unsigned long long fma2_(unsigned long long a,
                                                    unsigned long long b,
                                                    unsigned long long c) {
    unsigned long long d;
    asm("fma.rn.f32x2 %0, %1, %2, %3;" : "=l"(d) : "l"(a), "l"(b), "l"(c));
    return d;
}
__device__ __forceinline__ unsigned long long add2_(unsigned long long a,
                                                    unsigned long long b) {
    unsigned long long d;
    asm("add.rn.f32x2 %0, %1, %2;" : "=l"(d) : "l"(a), "l"(b));
    return d;
}
__device__ __forceinline__ unsigned long long dup2_(float x) {
    unsigned long long d;
    asm("mov.b64 %0, {%1, %1};" : "=l"(d) : "r"(__float_as_uint(x)));
    return d;
}
__device__ __forceinline__ unsigned long long pack2_(float lo, float hi) {
    unsigned long long d;
    asm("mov.b64 %0, {%1, %2};" : "=l"(d) : "r"(__float_as_uint(lo)), "r"(__float_as_uint(hi)));
    return d;
}
__device__ __forceinline__ void unpack2_(unsigned long long v, float& lo, float& hi) {
    unsigned a, b;
    asm("mov.b64 {%0, %1}, %2;" : "=r"(a), "=r"(b) : "l"(v));
    lo = __uint_as_float(a); hi = __uint_as_float(b);
}
__device__ __forceinline__ float sigmoidf_(float x) {
    return 1.0f / (1.0f + __expf(-x));
}
__device__ __forceinline__ float tanh_fast_(float x) {   // 2*sigmoid(2x)-1
    return __fmaf_rn(2.0f, 1.0f / (1.0f + __expf(-2.0f * x)), -1.0f);
}

// Volatile tagged 8B load/store (single transaction -> no tearing)
__device__ __forceinline__ float2 vld2_(const float2* p) {
    float2 v;
    asm volatile("ld.volatile.global.v2.f32 {%0,%1}, [%2];"
                 : "=f"(v.x), "=f"(v.y) : "l"(p));
    return v;
}
__device__ __forceinline__ void vst2_(float2* p, float h, unsigned tag) {
    asm volatile("st.volatile.global.v2.f32 [%0], {%1,%2};"
                 :: "l"(p), "f"(h), "f"(__uint_as_float(tag)) : "memory");
}

// ---------------------------------------------------------------------------
// Pre-kernel: g_xz[t][col][b] = bias + x[b,t,:] . w_ih[4 gate rows of col, :]
// ---------------------------------------------------------------------------
#define PG_COLS 32
__global__ void __launch_bounds__(256) xz_gemm_kernel(
    const float* __restrict__ x, const float* __restrict__ w_ih,
    const float* __restrict__ bias)
{
    extern __shared__ float ps[];
    float (*xs)[65] = (float(*)[65])ps;          // [b][k], padded
    float* ws = ps + 64 * 65;                    // [c][k][q]

    const int t       = blockIdx.y;
    const int colbase = blockIdx.x * PG_COLS;
    const int tid     = threadIdx.x;

    for (int i = tid; i < 64 * 16; i += 256) {
        int b = i >> 4, k4 = i & 15;
        float4 v = *(const float4*)(x + (size_t)b * (T_LEN * XDIM) + (size_t)t * XDIM + 4 * k4);
        xs[b][4 * k4 + 0] = v.x; xs[b][4 * k4 + 1] = v.y;
        xs[b][4 * k4 + 2] = v.z; xs[b][4 * k4 + 3] = v.w;
    }
    for (int i = tid; i < PG_COLS * 64 * 4; i += 256) {
        int q = i & 3, k = (i >> 2) & 63, c = i >> 8;
        ws[i] = w_ih[(q * HID + colbase + c) * XDIM + k];
    }
    __syncthreads();

    const int b  = tid & 63;
    const int cg = tid >> 6;
    unsigned long long acc01[8], acc23[8];
    #pragma unroll
    for (int c8 = 0; c8 < 8; ++c8) {
        int col = colbase + cg * 8 + c8;
        acc01[c8] = pack2_(bias[0 * HID + col], bias[1 * HID + col]);
        acc23[c8] = pack2_(bias[2 * HID + col], bias[3 * HID + col]);
    }
    #pragma unroll 4
    for (int k = 0; k < 64; ++k) {
        unsigned long long xv = dup2_(xs[b][k]);
        #pragma unroll
        for (int c8 = 0; c8 < 8; ++c8) {
            ulonglong2 w = *(ulonglong2*)&ws[((cg * 8 + c8) * 64 + k) * 4];
            acc01[c8] = fma2_(w.x, xv, acc01[c8]);
            acc23[c8] = fma2_(w.y, xv, acc23[c8]);
        }
    }
    #pragma unroll
    for (int c8 = 0; c8 < 8; ++c8) {
        int col = colbase + cg * 8 + c8;
        float4 o;
        unpack2_(acc01[c8], o.x, o.y);
        unpack2_(acc23[c8], o.z, o.w);
        g_xz[((size_t)t * HID + col) * BATCH + b] = o;
    }
}

// ---------------------------------------------------------------------------
// Persistent LSTM, tagged dataflow: direct-from-L2 k-sliced GEMV + SINGLE-
// STAGE reduce.
//   CTA (s,beta): cols [4s,4s+4), batches [32beta,32beta+32).
//   Warp w: k-slice [16w,16w+16), lane = batch. Tagged h consumed straight
//   from L2 (coalesced, MLP=16; stale re-loads predicated), FMA all 4 cols
//   x 4 gates from registers, partial -> p1[w][c]. ONE __syncthreads.
//   Owner warps 0-3 (one per SMSP; warp c owns col 4s+c) read all 16
//   partials, tree-add, + xz, pointwise, publish; the other 12 warps loop
//   straight back to next step's loads.
//   p1 depth-2 by t&1. WAR at distance 2: every CTA has a warp covering
//   every col, so any CTA's sync(t+1) happens-after our owner's p1(t)
//   reads (via our h(t+1) publish), before any p1(t+2) write.
// ---------------------------------------------------------------------------
__global__ void __launch_bounds__(NTHR, 1) lstm_kernel(
    const float* __restrict__ w_hh, float* __restrict__ out)
{
    extern __shared__ __align__(16) float smem[];
    float* wsm = smem;                                     // [256k][4c][4g] 16KB
    ulonglong2* part1 = (ulonglong2*)(smem + 4 * KH * 4);  // [2][16w][4c][32l] 64KB
    __shared__ unsigned sh_epoch;

    const int tid   = threadIdx.x;
    const int warp  = tid >> 5;
    const int lane  = tid & 31;
    const int cw    = warp & 3;           // col duty (owners: warp==cw)
    const int s     = blockIdx.x & 63;
    const int beta  = blockIdx.x >> 6;
    const int col   = 4 * s + cw;
    const int b     = 32 * beta + lane;
    const bool owner = (warp < 4);

    if (tid == 0) sh_epoch = atomicAdd(&g_epoch, 1u) >> 7;   // /NCTA -> replay id

    // Weights: wsm[((k*4 + c)*4) + q] = w_hh[q*HID + 4s+c][k], gates i,f,g,o
    for (int idx = tid; idx < 4 * KH * 4; idx += NTHR) {
        int q = idx & 3, c = (idx >> 2) & 3, k = idx >> 4;
        wsm[idx] = w_hh[(q * HID + 4 * s + c) * HID + k];
    }
    __syncthreads();
    const unsigned epoch = sh_epoch;
    const unsigned tag0  = epoch * (unsigned)(T_LEN + 1) + 1u;  // tag(h_t)=tag0+t

    float c_reg = 0.0f;
    float4 xz = make_float4(0.f, 0.f, 0.f, 0.f);
    float2* gh2 = &g_h2[0][0][0];
    if (owner) {
        vst2_(gh2 + (size_t)col * BATCH + b, 0.0f, tag0);     // h(0)=0, slot 0
        xz = __ldcg(&g_xz[(size_t)col * BATCH + b]);          // xz(t=0)
    }

    const size_t out_base = (size_t)b * (T_LEN * HID) + col;
    const ulonglong2* wk = (const ulonglong2*)wsm + warp * KW * 4;   // [k16][c4]
    const float2* src0 = gh2 + (size_t)(warp * KW) * BATCH + b;      // slot 0

    for (int t = 0; t < T_LEN; ++t) {
        const unsigned exp = tag0 + (unsigned)t;
        const int buf = t & 1;
        const float2* src = src0 + (size_t)buf * (KH * BATCH);
        ulonglong2* p1 = part1 + (size_t)buf * (16 * 4 * 32);

        // Direct tagged consume: fire all 16 (MLP=16, coalesced per k),
        // then predicated re-load of stale values per round.
        float2 v[KW];
        #pragma unroll
        for (int i = 0; i < KW; ++i) v[i] = vld2_(src + i * BATCH);
        while (true) {
            bool ok = true;
            #pragma unroll
            for (int i = 0; i < KW; ++i)
                ok &= (__float_as_uint(v[i].y) == exp);
            if (__all_sync(0xffffffffu, ok)) break;
            #pragma unroll
            for (int i = 0; i < KW; ++i)
                if (__float_as_uint(v[i].y) != exp)
                    v[i] = vld2_(src + i * BATCH);
        }

        // GEMV from registers: per k = dup + 4 wgt LDS.128 (bcast) + 8 FFMA2
        unsigned long long a01[4] = {0ull, 0ull, 0ull, 0ull};
        unsigned long long a23[4] = {0ull, 0ull, 0ull, 0ull};
        #pragma unroll
        for (int k = 0; k < KW; ++k) {
            unsigned long long hv2 = dup2_(v[k].x);
            #pragma unroll
            for (int c = 0; c < 4; ++c) {
                ulonglong2 w2 = wk[k * 4 + c];
                a01[c] = fma2_(w2.x, hv2, a01[c]);
                a23[c] = fma2_(w2.y, hv2, a23[c]);
            }
        }
        #pragma unroll
        for (int c = 0; c < 4; ++c) {
            ulonglong2 pv; pv.x = a01[c]; pv.y = a23[c];
            p1[(warp * 4 + c) * 32 + lane] = pv;
        }
        __syncthreads();                                     // all partials in

        if (owner) {   // warp cw: gather 16 partials for col cw, tree-add
            ulonglong2 r[16];
            #pragma unroll
            for (int w = 0; w < 16; ++w)
                r[w] = p1[(w * 4 + cw) * 32 + lane];
            #pragma unroll
            for (int d = 8; d >= 1; d >>= 1)
                #pragma unroll
                for (int w = 0; w < d; ++w) {                // balanced tree
                    r[w].x = add2_(r[w].x, r[w + d].x);
                    r[w].y = add2_(r[w].y, r[w + d].y);
                }
            unsigned long long acc01 = add2_(r[0].x, pack2_(xz.x, xz.y));
            unsigned long long acc23 = add2_(r[0].y, pack2_(xz.z, xz.w));
            float a0, a1, a2, a3;
            unpack2_(acc01, a0, a1);
            unpack2_(acc23, a2, a3);

            const float ig = sigmoidf_(a0);
            const float fg = sigmoidf_(a1);
            const float gg = tanh_fast_(a2);
            const float og = sigmoidf_(a3);
            c_reg = fmaf(fg, c_reg, ig * gg);
            const float h = og * tanh_fast_(c_reg);

            // Publish FIRST (consumers spin on this), then sideband stores.
            vst2_(gh2 + (size_t)((t + 1) & 1) * (KH * BATCH)
                      + (size_t)col * BATCH + b, h, exp + 1u);
            out[out_base + (size_t)t * HID] = h;
            if (t + 1 < T_LEN)
                xz = __ldcg(&g_xz[((size_t)(t + 1) * HID + col) * BATCH + b]);
        }
        // Non-owner warps fall straight through to the next step's loads,
        // overlapping the owners' reduce/pointwise/publish.
    }
}

// ---------------------------------------------------------------------------
extern "C" void kernel_launch(void* const* d_in, const int* in_sizes, int n_in,
                              void* d_out, int out_size) {
    (void)in_sizes; (void)n_in; (void)out_size;
    const float* x    = (const float*)d_in[0];
    const float* w_ih = (const float*)d_in[1];
    const float* w_hh = (const float*)d_in[2];
    const float* bias = (const float*)d_in[3];
    float* out = (float*)d_out;

    const int pg_smem = (64 * 65 + PG_COLS * 64 * 4) * (int)sizeof(float);
    cudaFuncSetAttribute(xz_gemm_kernel,
                         cudaFuncAttributeMaxDynamicSharedMemorySize, pg_smem);
    const int ls_smem = 4 * KH * 4 * (int)sizeof(float)
                        + 2 * 16 * 4 * 32 * (int)sizeof(ulonglong2);  // 16+64 KB
    cudaFuncSetAttribute(lstm_kernel,
                         cudaFuncAttributeMaxDynamicSharedMemorySize, ls_smem);

    dim3 pg_grid(HID / PG_COLS, T_LEN);
    xz_gemm_kernel<<<pg_grid, 256, pg_smem>>>(x, w_ih, bias);
    lstm_kernel<<<NCTA, NTHR, ls_smem>>>(w_hh, out);
}

// round 14
// speedup vs baseline: 1.9595x; 1.0014x over previous
#include <cuda_runtime.h>

#define T_LEN 2048
#define BATCH 64
#define XDIM  64
#define HID   256
#define KH    256            // recurrent K (x part precomputed)
#define KW    16             // K per warp (GEMV granularity)

#define NCTA  128            // 2 batch-halves x 64 column-slices
#define NTHR  512            // 16 warps, warp w = k-slice [16w,16w+16)

// Static device scratch (no cudaMalloc anywhere)
__device__ float4 g_xz[(size_t)T_LEN * HID * BATCH];   // [t][col][b] pre-activations
__device__ __align__(16) float2 g_h2[2][KH][BATCH];    // tagged h: {h, tag}
__device__ unsigned g_epoch;                           // replay epoch counter

// ---------------- packed f32x2 helpers ----------------
__device__ __forceinline__ unsigned long long fma2_(unsigned long long a,
                                                    unsigned long long b,
                                                    unsigned long long c) {
    unsigned long long d;
    asm("fma.rn.f32x2 %0, %1, %2, %3;" : "=l"(d) : "l"(a), "l"(b), "l"(c));
    return d;
}
__device__ __forceinline__ unsigned long long add2_(unsigned long long a,
                                                    unsigned long long b) {
    unsigned long long d;
    asm("add.rn.f32x2 %0, %1, %2;" : "=l"(d) : "l"(a), "l"(b));
    return d;
}
__device__ __forceinline__ unsigned long long dup2_(float x) {
    unsigned long long d;
    asm("mov.b64 %0, {%1, %1};" : "=l"(d) : "r"(__float_as_uint(x)));
    return d;
}
__device__ __forceinline__ unsigned long long pack2_(float lo, float hi) {
    unsigned long long d;
    asm("mov.b64 %0, {%1, %2};" : "=l"(d) : "r"(__float_as_uint(lo)), "r"(__float_as_uint(hi)));
    return d;
}
__device__ __forceinline__ void unpack2_(unsigned long long v, float& lo, float& hi) {
    unsigned a, b;
    asm("mov.b64 {%0, %1}, %2;" : "=r"(a), "=r"(b) : "l"(v));
    lo = __uint_as_float(a); hi = __uint_as_float(b);
}
__device__ __forceinline__ float sigmoidf_(float x) {
    return 1.0f / (1.0f + __expf(-x));
}
__device__ __forceinline__ float tanh_fast_(float x) {   // 2*sigmoid(2x)-1
    return __fmaf_rn(2.0f, 1.0f / (1.0f + __expf(-2.0f * x)), -1.0f);
}

// Volatile tagged 8B load/store (single transaction -> no tearing)
__device__ __forceinline__ float2 vld2_(const float2* p) {
    float2 v;
    asm volatile("ld.volatile.global.v2.f32 {%0,%1}, [%2];"
                 : "=f"(v.x), "=f"(v.y) : "l"(p));
    return v;
}
__device__ __forceinline__ void vst2_(float2* p, float h, unsigned tag) {
    asm volatile("st.volatile.global.v2.f32 [%0], {%1,%2};"
                 :: "l"(p), "f"(h), "f"(__uint_as_float(tag)) : "memory");
}

// ---------------------------------------------------------------------------
// Pre-kernel: g_xz[t][col][b] = bias + x[b,t,:] . w_ih[4 gate rows of col, :]
// Retiled: 256 thr = 32 batch-pairs x 8 col-groups; each thread does
// 2 batches (b0, b0+32) x 8 cols -> weight LDS amortized over 2 batches.
// ---------------------------------------------------------------------------
#define PG_COLS 64
__global__ void __launch_bounds__(256) xz_gemm_kernel(
    const float* __restrict__ x, const float* __restrict__ w_ih,
    const float* __restrict__ bias)
{
    extern __shared__ float ps[];
    float (*xs)[65] = (float(*)[65])ps;          // [b][k], padded (16.6 KB)
    float* ws = ps + 64 * 65;                    // [c64][k64][q4]   (64 KB)

    const int t       = blockIdx.y;
    const int colbase = blockIdx.x * PG_COLS;
    const int tid     = threadIdx.x;

    for (int i = tid; i < 64 * 16; i += 256) {
        int b = i >> 4, k4 = i & 15;
        float4 v = *(const float4*)(x + (size_t)b * (T_LEN * XDIM) + (size_t)t * XDIM + 4 * k4);
        xs[b][4 * k4 + 0] = v.x; xs[b][4 * k4 + 1] = v.y;
        xs[b][4 * k4 + 2] = v.z; xs[b][4 * k4 + 3] = v.w;
    }
    for (int i = tid; i < PG_COLS * 64 * 4; i += 256) {
        int q = i & 3, k = (i >> 2) & 63, c = i >> 8;
        ws[i] = w_ih[(q * HID + colbase + c) * XDIM + k];
    }
    __syncthreads();

    const int b0 = tid & 31;                     // batches b0 and b0+32
    const int cg = tid >> 5;                     // 0..7 -> cols cg*8..cg*8+7
    unsigned long long a01[8][2], a23[8][2];
    #pragma unroll
    for (int c8 = 0; c8 < 8; ++c8) {
        int col = colbase + cg * 8 + c8;
        unsigned long long b01 = pack2_(bias[0 * HID + col], bias[1 * HID + col]);
        unsigned long long b23 = pack2_(bias[2 * HID + col], bias[3 * HID + col]);
        a01[c8][0] = b01; a01[c8][1] = b01;
        a23[c8][0] = b23; a23[c8][1] = b23;
    }
    #pragma unroll 2
    for (int k = 0; k < 64; ++k) {
        unsigned long long xv0 = dup2_(xs[b0][k]);
        unsigned long long xv1 = dup2_(xs[b0 + 32][k]);
        #pragma unroll
        for (int c8 = 0; c8 < 8; ++c8) {
            ulonglong2 w = *(ulonglong2*)&ws[((cg * 8 + c8) * 64 + k) * 4];
            a01[c8][0] = fma2_(w.x, xv0, a01[c8][0]);
            a23[c8][0] = fma2_(w.y, xv0, a23[c8][0]);
            a01[c8][1] = fma2_(w.x, xv1, a01[c8][1]);
            a23[c8][1] = fma2_(w.y, xv1, a23[c8][1]);
        }
    }
    #pragma unroll
    for (int c8 = 0; c8 < 8; ++c8) {
        int col = colbase + cg * 8 + c8;
        float4 o0, o1;
        unpack2_(a01[c8][0], o0.x, o0.y);
        unpack2_(a23[c8][0], o0.z, o0.w);
        unpack2_(a01[c8][1], o1.x, o1.y);
        unpack2_(a23[c8][1], o1.z, o1.w);
        g_xz[((size_t)t * HID + col) * BATCH + b0]      = o0;
        g_xz[((size_t)t * HID + col) * BATCH + b0 + 32] = o1;
    }
}

// ---------------------------------------------------------------------------
// Persistent LSTM, tagged dataflow: direct-from-L2 k-sliced GEMV + single-
// stage reduce (R13 structure) + poll backoff.
// ---------------------------------------------------------------------------
__global__ void __launch_bounds__(NTHR, 1) lstm_kernel(
    const float* __restrict__ w_hh, float* __restrict__ out)
{
    extern __shared__ __align__(16) float smem[];
    float* wsm = smem;                                     // [256k][4c][4g] 16KB
    ulonglong2* part1 = (ulonglong2*)(smem + 4 * KH * 4);  // [2][16w][4c][32l] 64KB
    __shared__ unsigned sh_epoch;

    const int tid   = threadIdx.x;
    const int warp  = tid >> 5;
    const int lane  = tid & 31;
    const int cw    = warp & 3;           // col duty (owners: warp==cw)
    const int s     = blockIdx.x & 63;
    const int beta  = blockIdx.x >> 6;
    const int col   = 4 * s + cw;
    const int b     = 32 * beta + lane;
    const bool owner = (warp < 4);

    if (tid == 0) sh_epoch = atomicAdd(&g_epoch, 1u) >> 7;   // /NCTA -> replay id

    // Weights: wsm[((k*4 + c)*4) + q] = w_hh[q*HID + 4s+c][k], gates i,f,g,o
    for (int idx = tid; idx < 4 * KH * 4; idx += NTHR) {
        int q = idx & 3, c = (idx >> 2) & 3, k = idx >> 4;
        wsm[idx] = w_hh[(q * HID + 4 * s + c) * HID + k];
    }
    __syncthreads();
    const unsigned epoch = sh_epoch;
    const unsigned tag0  = epoch * (unsigned)(T_LEN + 1) + 1u;  // tag(h_t)=tag0+t

    float c_reg = 0.0f;
    float4 xz = make_float4(0.f, 0.f, 0.f, 0.f);
    float2* gh2 = &g_h2[0][0][0];
    if (owner) {
        vst2_(gh2 + (size_t)col * BATCH + b, 0.0f, tag0);     // h(0)=0, slot 0
        xz = __ldcg(&g_xz[(size_t)col * BATCH + b]);          // xz(t=0)
    }

    const size_t out_base = (size_t)b * (T_LEN * HID) + col;
    const ulonglong2* wk = (const ulonglong2*)wsm + warp * KW * 4;   // [k16][c4]
    const float2* src0 = gh2 + (size_t)(warp * KW) * BATCH + b;      // slot 0

    for (int t = 0; t < T_LEN; ++t) {
        const unsigned exp = tag0 + (unsigned)t;
        const int buf = t & 1;
        const float2* src = src0 + (size_t)buf * (KH * BATCH);
        ulonglong2* p1 = part1 + (size_t)buf * (16 * 4 * 32);

        // Direct tagged consume: fire all 16 (MLP=16, coalesced per k);
        // re-fire only stale values. From the 2nd failed round on, back off
        // with a short nanosleep to keep junk polls off the L1tex path.
        float2 v[KW];
        #pragma unroll
        for (int i = 0; i < KW; ++i) v[i] = vld2_(src + i * BATCH);
        int round = 0;
        while (true) {
            bool ok = true;
            #pragma unroll
            for (int i = 0; i < KW; ++i)
                ok &= (__float_as_uint(v[i].y) == exp);
            if (__all_sync(0xffffffffu, ok)) break;
            if (round++ > 0) __nanosleep(64);
            #pragma unroll
            for (int i = 0; i < KW; ++i)
                if (__float_as_uint(v[i].y) != exp)
                    v[i] = vld2_(src + i * BATCH);
        }

        // GEMV from registers: per k = dup + 4 wgt LDS.128 (bcast) + 8 FFMA2
        unsigned long long a01[4] = {0ull, 0ull, 0ull, 0ull};
        unsigned long long a23[4] = {0ull, 0ull, 0ull, 0ull};
        #pragma unroll
        for (int k = 0; k < KW; ++k) {
            unsigned long long hv2 = dup2_(v[k].x);
            #pragma unroll
            for (int c = 0; c < 4; ++c) {
                ulonglong2 w2 = wk[k * 4 + c];
                a01[c] = fma2_(w2.x, hv2, a01[c]);
                a23[c] = fma2_(w2.y, hv2, a23[c]);
            }
        }
        #pragma unroll
        for (int c = 0; c < 4; ++c) {
            ulonglong2 pv; pv.x = a01[c]; pv.y = a23[c];
            p1[(warp * 4 + c) * 32 + lane] = pv;
        }
        __syncthreads();                                     // all partials in

        if (owner) {   // warp cw: gather 16 partials for col cw, tree-add
            ulonglong2 r[16];
            #pragma unroll
            for (int w = 0; w < 16; ++w)
                r[w] = p1[(w * 4 + cw) * 32 + lane];
            #pragma unroll
            for (int d = 8; d >= 1; d >>= 1)
                #pragma unroll
                for (int w = 0; w < d; ++w) {                // balanced tree
                    r[w].x = add2_(r[w].x, r[w + d].x);
                    r[w].y = add2_(r[w].y, r[w + d].y);
                }
            unsigned long long acc01 = add2_(r[0].x, pack2_(xz.x, xz.y));
            unsigned long long acc23 = add2_(r[0].y, pack2_(xz.z, xz.w));
            float a0, a1, a2, a3;
            unpack2_(acc01, a0, a1);
            unpack2_(acc23, a2, a3);

            const float ig = sigmoidf_(a0);
            const float fg = sigmoidf_(a1);
            const float gg = tanh_fast_(a2);
            const float og = sigmoidf_(a3);
            c_reg = fmaf(fg, c_reg, ig * gg);
            const float h = og * tanh_fast_(c_reg);

            // Publish FIRST (consumers spin on this), then sideband stores.
            vst2_(gh2 + (size_t)((t + 1) & 1) * (KH * BATCH)
                      + (size_t)col * BATCH + b, h, exp + 1u);
            out[out_base + (size_t)t * HID] = h;
            if (t + 1 < T_LEN)
                xz = __ldcg(&g_xz[((size_t)(t + 1) * HID + col) * BATCH + b]);
        }
        // Non-owner warps fall straight through to the next step's loads,
        // overlapping the owners' reduce/pointwise/publish.
    }
}

// ---------------------------------------------------------------------------
extern "C" void kernel_launch(void* const* d_in, const int* in_sizes, int n_in,
                              void* d_out, int out_size) {
    (void)in_sizes; (void)n_in; (void)out_size;
    const float* x    = (const float*)d_in[0];
    const float* w_ih = (const float*)d_in[1];
    const float* w_hh = (const float*)d_in[2];
    const float* bias = (const float*)d_in[3];
    float* out = (float*)d_out;

    const int pg_smem = (64 * 65 + PG_COLS * 64 * 4) * (int)sizeof(float); // ~82 KB
    cudaFuncSetAttribute(xz_gemm_kernel,
                         cudaFuncAttributeMaxDynamicSharedMemorySize, pg_smem);
    const int ls_smem = 4 * KH * 4 * (int)sizeof(float)
                        + 2 * 16 * 4 * 32 * (int)sizeof(ulonglong2);  // 16+64 KB
    cudaFuncSetAttribute(lstm_kernel,
                         cudaFuncAttributeMaxDynamicSharedMemorySize, ls_smem);

    dim3 pg_grid(HID / PG_COLS, T_LEN);
    xz_gemm_kernel<<<pg_grid, 256, pg_smem>>>(x, w_ih, bias);
    lstm_kernel<<<NCTA, NTHR, ls_smem>>>(w_hh, out);
}

// round 15
// speedup vs baseline: 2.0696x; 1.0562x over previous
#include <cuda_runtime.h>

#define T_LEN 2048
#define BATCH 64
#define XDIM  64
#define HID   256
#define KH    256            // recurrent K (x part precomputed)
#define KW    16             // K per warp (GEMV granularity)

#define NCTA  128            // 2 batch-halves x 64 column-slices
#define NTHR  512            // 16 warps, warp w = k-slice [16w,16w+16)

// Static device scratch (no cudaMalloc anywhere)
__device__ float4 g_xz[(size_t)T_LEN * HID * BATCH];   // [t][col][b] pre-activations
__device__ __align__(16) float2 g_h2[2][KH][BATCH];    // tagged h: {h, tag}
__device__ unsigned g_epoch;                           // replay epoch counter

// ---------------- packed f32x2 helpers ----------------
__device__ __forceinline__ unsigned long long fma2_(unsigned long long a,
                                                    unsigned long long b,
                                                    unsigned long long c) {
    unsigned long long d;
    asm("fma.rn.f32x2 %0, %1, %2, %3;" : "=l"(d) : "l"(a), "l"(b), "l"(c));
    return d;
}
__device__ __forceinline__ unsigned long long add2_(unsigned long long a,
                                                    unsigned long long b) {
    unsigned long long d;
    asm("add.rn.f32x2 %0, %1, %2;" : "=l"(d) : "l"(a), "l"(b));
    return d;
}
__device__ __forceinline__ unsigned long long dup2_(float x) {
    unsigned long long d;
    asm("mov.b64 %0, {%1, %1};" : "=l"(d) : "r"(__float_as_uint(x)));
    return d;
}
__device__ __forceinline__ unsigned long long pack2_(float lo, float hi) {
    unsigned long long d;
    asm("mov.b64 %0, {%1, %2};" : "=l"(d) : "r"(__float_as_uint(lo)), "r"(__float_as_uint(hi)));
    return d;
}
__device__ __forceinline__ void unpack2_(unsigned long long v, float& lo, float& hi) {
    unsigned a, b;
    asm("mov.b64 {%0, %1}, %2;" : "=r"(a), "=r"(b) : "l"(v));
    lo = __uint_as_float(a); hi = __uint_as_float(b);
}
// HW tanh (MUFU.TANH, sm_75+): 1 op instead of ex2+add+rcp chain
__device__ __forceinline__ float tanh_hw_(float x) {
    float y;
    asm("tanh.approx.f32 %0, %1;" : "=f"(y) : "f"(x));
    return y;
}
__device__ __forceinline__ float sigmoid_hw_(float x) {   // 0.5*tanh(x/2)+0.5
    return __fmaf_rn(0.5f, tanh_hw_(0.5f * x), 0.5f);
}

// Volatile tagged 8B load/store (single transaction -> no tearing)
__device__ __forceinline__ float2 vld2_(const float2* p) {
    float2 v;
    asm volatile("ld.volatile.global.v2.f32 {%0,%1}, [%2];"
                 : "=f"(v.x), "=f"(v.y) : "l"(p));
    return v;
}
__device__ __forceinline__ void vst2_(float2* p, float h, unsigned tag) {
    asm volatile("st.volatile.global.v2.f32 [%0], {%1,%2};"
                 :: "l"(p), "f"(h), "f"(__uint_as_float(tag)) : "memory");
}

// ---------------------------------------------------------------------------
// Pre-kernel: g_xz[t][col][b] = bias + x[b,t,:] . w_ih[4 gate rows of col, :]
// Retiled (R14, proven): thread = 2 batches (b0, b0+32) x 8 cols.
// ---------------------------------------------------------------------------
#define PG_COLS 64
__global__ void __launch_bounds__(256) xz_gemm_kernel(
    const float* __restrict__ x, const float* __restrict__ w_ih,
    const float* __restrict__ bias)
{
    extern __shared__ float ps[];
    float (*xs)[65] = (float(*)[65])ps;          // [b][k], padded (16.6 KB)
    float* ws = ps + 64 * 65;                    // [c64][k64][q4]   (64 KB)

    const int t       = blockIdx.y;
    const int colbase = blockIdx.x * PG_COLS;
    const int tid     = threadIdx.x;

    for (int i = tid; i < 64 * 16; i += 256) {
        int b = i >> 4, k4 = i & 15;
        float4 v = *(const float4*)(x + (size_t)b * (T_LEN * XDIM) + (size_t)t * XDIM + 4 * k4);
        xs[b][4 * k4 + 0] = v.x; xs[b][4 * k4 + 1] = v.y;
        xs[b][4 * k4 + 2] = v.z; xs[b][4 * k4 + 3] = v.w;
    }
    for (int i = tid; i < PG_COLS * 64 * 4; i += 256) {
        int q = i & 3, k = (i >> 2) & 63, c = i >> 8;
        ws[i] = w_ih[(q * HID + colbase + c) * XDIM + k];
    }
    __syncthreads();

    const int b0 = tid & 31;                     // batches b0 and b0+32
    const int cg = tid >> 5;                     // 0..7 -> cols cg*8..cg*8+7
    unsigned long long a01[8][2], a23[8][2];
    #pragma unroll
    for (int c8 = 0; c8 < 8; ++c8) {
        int col = colbase + cg * 8 + c8;
        unsigned long long b01 = pack2_(bias[0 * HID + col], bias[1 * HID + col]);
        unsigned long long b23 = pack2_(bias[2 * HID + col], bias[3 * HID + col]);
        a01[c8][0] = b01; a01[c8][1] = b01;
        a23[c8][0] = b23; a23[c8][1] = b23;
    }
    #pragma unroll 2
    for (int k = 0; k < 64; ++k) {
        unsigned long long xv0 = dup2_(xs[b0][k]);
        unsigned long long xv1 = dup2_(xs[b0 + 32][k]);
        #pragma unroll
        for (int c8 = 0; c8 < 8; ++c8) {
            ulonglong2 w = *(ulonglong2*)&ws[((cg * 8 + c8) * 64 + k) * 4];
            a01[c8][0] = fma2_(w.x, xv0, a01[c8][0]);
            a23[c8][0] = fma2_(w.y, xv0, a23[c8][0]);
            a01[c8][1] = fma2_(w.x, xv1, a01[c8][1]);
            a23[c8][1] = fma2_(w.y, xv1, a23[c8][1]);
        }
    }
    #pragma unroll
    for (int c8 = 0; c8 < 8; ++c8) {
        int col = colbase + cg * 8 + c8;
        float4 o0, o1;
        unpack2_(a01[c8][0], o0.x, o0.y);
        unpack2_(a23[c8][0], o0.z, o0.w);
        unpack2_(a01[c8][1], o1.x, o1.y);
        unpack2_(a23[c8][1], o1.z, o1.w);
        g_xz[((size_t)t * HID + col) * BATCH + b0]      = o0;
        g_xz[((size_t)t * HID + col) * BATCH + b0 + 32] = o1;
    }
}

// ---------------------------------------------------------------------------
// Persistent LSTM, tagged dataflow: direct-from-L2 k-sliced GEMV with
// FMA-on-arrival groups + single-stage reduce + HW-tanh pointwise.
// ---------------------------------------------------------------------------
__global__ void __launch_bounds__(NTHR, 1) lstm_kernel(
    const float* __restrict__ w_hh, float* __restrict__ out)
{
    extern __shared__ __align__(16) float smem[];
    float* wsm = smem;                                     // [256k][4c][4g] 16KB
    ulonglong2* part1 = (ulonglong2*)(smem + 4 * KH * 4);  // [2][16w][4c][32l] 64KB
    __shared__ unsigned sh_epoch;

    const int tid   = threadIdx.x;
    const int warp  = tid >> 5;
    const int lane  = tid & 31;
    const int cw    = warp & 3;           // col duty (owners: warp==cw)
    const int s     = blockIdx.x & 63;
    const int beta  = blockIdx.x >> 6;
    const int col   = 4 * s + cw;
    const int b     = 32 * beta + lane;
    const bool owner = (warp < 4);

    if (tid == 0) sh_epoch = atomicAdd(&g_epoch, 1u) >> 7;   // /NCTA -> replay id

    // Weights: wsm[((k*4 + c)*4) + q] = w_hh[q*HID + 4s+c][k], gates i,f,g,o
    for (int idx = tid; idx < 4 * KH * 4; idx += NTHR) {
        int q = idx & 3, c = (idx >> 2) & 3, k = idx >> 4;
        wsm[idx] = w_hh[(q * HID + 4 * s + c) * HID + k];
    }
    __syncthreads();
    const unsigned epoch = sh_epoch;
    const unsigned tag0  = epoch * (unsigned)(T_LEN + 1) + 1u;  // tag(h_t)=tag0+t

    float c_reg = 0.0f;
    float4 xz = make_float4(0.f, 0.f, 0.f, 0.f);
    float2* gh2 = &g_h2[0][0][0];
    if (owner) {
        vst2_(gh2 + (size_t)col * BATCH + b, 0.0f, tag0);     // h(0)=0, slot 0
        xz = __ldcg(&g_xz[(size_t)col * BATCH + b]);          // xz(t=0)
    }

    const size_t out_base = (size_t)b * (T_LEN * HID) + col;
    const ulonglong2* wk = (const ulonglong2*)wsm + warp * KW * 4;   // [k16][c4]
    const float2* src0 = gh2 + (size_t)(warp * KW) * BATCH + b;      // slot 0

    for (int t = 0; t < T_LEN; ++t) {
        const unsigned exp = tag0 + (unsigned)t;
        const int buf = t & 1;
        const float2* src = src0 + (size_t)buf * (KH * BATCH);
        ulonglong2* p1 = part1 + (size_t)buf * (16 * 4 * 32);

        // Fire all 16 tagged loads (MLP=16, coalesced per k) up front.
        float2 v[KW];
        #pragma unroll
        for (int i = 0; i < KW; ++i) v[i] = vld2_(src + i * BATCH);

        // FMA-on-arrival: consume in 4 groups of 4; early groups' FMA
        // overlaps later groups' in-flight detect.
        unsigned long long a01[4] = {0ull, 0ull, 0ull, 0ull};
        unsigned long long a23[4] = {0ull, 0ull, 0ull, 0ull};
        #pragma unroll
        for (int g = 0; g < 4; ++g) {
            while (true) {
                bool ok = true;
                #pragma unroll
                for (int j = 0; j < 4; ++j)
                    ok &= (__float_as_uint(v[g * 4 + j].y) == exp);
                if (__all_sync(0xffffffffu, ok)) break;
                #pragma unroll
                for (int j = 0; j < 4; ++j)
                    if (__float_as_uint(v[g * 4 + j].y) != exp)
                        v[g * 4 + j] = vld2_(src + (g * 4 + j) * BATCH);
            }
            #pragma unroll
            for (int j = 0; j < 4; ++j) {
                int k = g * 4 + j;
                unsigned long long hv2 = dup2_(v[k].x);
                #pragma unroll
                for (int c = 0; c < 4; ++c) {
                    ulonglong2 w2 = wk[k * 4 + c];
                    a01[c] = fma2_(w2.x, hv2, a01[c]);
                    a23[c] = fma2_(w2.y, hv2, a23[c]);
                }
            }
        }
        #pragma unroll
        for (int c = 0; c < 4; ++c) {
            ulonglong2 pv; pv.x = a01[c]; pv.y = a23[c];
            p1[(warp * 4 + c) * 32 + lane] = pv;
        }
        __syncthreads();                                     // all partials in

        if (owner) {   // warp cw: gather 16 partials for col cw, tree-add
            ulonglong2 r[16];
            #pragma unroll
            for (int w = 0; w < 16; ++w)
                r[w] = p1[(w * 4 + cw) * 32 + lane];
            #pragma unroll
            for (int d = 8; d >= 1; d >>= 1)
                #pragma unroll
                for (int w = 0; w < d; ++w) {                // balanced tree
                    r[w].x = add2_(r[w].x, r[w + d].x);
                    r[w].y = add2_(r[w].y, r[w + d].y);
                }
            unsigned long long acc01 = add2_(r[0].x, pack2_(xz.x, xz.y));
            unsigned long long acc23 = add2_(r[0].y, pack2_(xz.z, xz.w));
            float a0, a1, a2, a3;
            unpack2_(acc01, a0, a1);
            unpack2_(acc23, a2, a3);

            const float ig = sigmoid_hw_(a0);
            const float fg = sigmoid_hw_(a1);
            const float gg = tanh_hw_(a2);
            const float og = sigmoid_hw_(a3);
            c_reg = fmaf(fg, c_reg, ig * gg);
            const float h = og * tanh_hw_(c_reg);

            // Publish FIRST (consumers spin on this), then sideband stores.
            vst2_(gh2 + (size_t)((t + 1) & 1) * (KH * BATCH)
                      + (size_t)col * BATCH + b, h, exp + 1u);
            out[out_base + (size_t)t * HID] = h;
            if (t + 1 < T_LEN)
                xz = __ldcg(&g_xz[((size_t)(t + 1) * HID + col) * BATCH + b]);
        }
        // Non-owner warps fall straight through to the next step's loads,
        // overlapping the owners' reduce/pointwise/publish.
    }
}

// ---------------------------------------------------------------------------
extern "C" void kernel_launch(void* const* d_in, const int* in_sizes, int n_in,
                              void* d_out, int out_size) {
    (void)in_sizes; (void)n_in; (void)out_size;
    const float* x    = (const float*)d_in[0];
    const float* w_ih = (const float*)d_in[1];
    const float* w_hh = (const float*)d_in[2];
    const float* bias = (const float*)d_in[3];
    float* out = (float*)d_out;

    const int pg_smem = (64 * 65 + PG_COLS * 64 * 4) * (int)sizeof(float); // ~82 KB
    cudaFuncSetAttribute(xz_gemm_kernel,
                         cudaFuncAttributeMaxDynamicSharedMemorySize, pg_smem);
    const int ls_smem = 4 * KH * 4 * (int)sizeof(float)
                        + 2 * 16 * 4 * 32 * (int)sizeof(ulonglong2);  // 16+64 KB
    cudaFuncSetAttribute(lstm_kernel,
                         cudaFuncAttributeMaxDynamicSharedMemorySize, ls_smem);

    dim3 pg_grid(HID / PG_COLS, T_LEN);
    xz_gemm_kernel<<<pg_grid, 256, pg_smem>>>(x, w_ih, bias);
    lstm_kernel<<<NCTA, NTHR, ls_smem>>>(w_hh, out);
}